// round 12
// baseline (speedup 1.0000x reference)
#include <cuda_runtime.h>
#include <math.h>

#define D 4
#define H 16
#define DH 64

#define N_MAX 65536

// Scratch (device globals). 256B alignment -> whole 128B lines per node.
__device__ __align__(256) float4 g_xf4[N_MAX * (DH / 4)];    // transformed features
__device__ __align__(256) float4 g_uv4[N_MAX * 8];           // per-node u(16), v(16)
__device__ __align__(256) float4 g_agg4[N_MAX * (DH / 4)];   // message aggregation
__device__ float  g_deg[N_MAX];   // starts 0; K1 accumulates; k_final resets to 0

// ---------------------------------------------------------------------------
// K1 (fused): blocks [0, TB): node transform + u/v projection (smem-staged);
// blocks [TB, TB+DB): source-node out-degree atomics.
// ---------------------------------------------------------------------------
#define XSTR 68   // padded node row stride (floats): float4-aligned, conflict-free

__global__ void __launch_bounds__(256) k_transform_deg_uv(
        const float* __restrict__ x,
        const float* __restrict__ W1,
        const float* __restrict__ W2,
        const float* __restrict__ m1w,
        const int* __restrict__ ei,
        int N, int E, int TB) {
    __shared__ float W1s[16];
    __shared__ __align__(16) float W2s[256];
    __shared__ __align__(16) float xs[64 * XSTR];   // 64 nodes staged / xf overwrite
    // uv weights at row (q*4 + part): part-stride 68 = 4 (mod 32) -> conflict-free.
    __shared__ __align__(16) float wt[32 * XSTR];

    int tid = threadIdx.x;

    if (blockIdx.x >= TB) {
        int e = (blockIdx.x - TB) * 256 + tid;
        if (e < E) atomicAdd(&g_deg[ei[e]], 1.0f);
        return;
    }

    if (tid < 16) W1s[tid] = W1[tid];
    for (int i = tid; i < 256; i += 256) W2s[i] = W2[i];
    for (int i = tid; i < 32 * 64; i += 256) {
        int oi = i >> 6;
        int k  = i & 63;
        int part = oi >> 3;
        int q    = oi & 7;
        float wv = (oi < 16) ? m1w[oi * 128 + k]
                             : m1w[(oi - 16) * 128 + 64 + k];
        wt[(q * 4 + part) * XSTR + k] = wv;
    }

    int nbase = blockIdx.x * 64;
    int navail = N - nbase;
    int nloc = navail >= 64 ? 64 : navail;
    int total = nloc * 64;
#pragma unroll 4
    for (int i = tid; i < total; i += 256) {
        int nl = i >> 6;
        int k  = i & 63;
        xs[nl * XSTR + k] = x[(size_t)nbase * 64 + i];
    }
    __syncthreads();

    int nl = tid >> 2;           // local node 0..63
    int d  = tid & 3;
    int n  = nbase + nl;

    float4 o4[4];
    if (n < N) {
        const float* xr = xs + nl * XSTR;
        float tf[16];
#pragma unroll
        for (int f = 0; f < 16; ++f) tf[f] = 0.f;
#pragma unroll
        for (int dd = 0; dd < 4; ++dd) {
            float w = W1s[dd * 4 + d];
#pragma unroll
            for (int f = 0; f < 16; ++f) tf[f] += w * xr[dd * 16 + f];
        }
        const float4* W2s4 = (const float4*)W2s;
#pragma unroll
        for (int g4 = 0; g4 < 4; ++g4) o4[g4] = make_float4(0.f, 0.f, 0.f, 0.f);
#pragma unroll
        for (int f = 0; f < 16; ++f) {
            float tv = tf[f];
#pragma unroll
            for (int g4 = 0; g4 < 4; ++g4) {
                float4 wv = W2s4[f * 4 + g4];
                o4[g4].x += tv * wv.x;
                o4[g4].y += tv * wv.y;
                o4[g4].z += tv * wv.z;
                o4[g4].w += tv * wv.w;
            }
        }
    }
    __syncthreads();   // all xs reads done before overwrite

    if (n < N) {
        float4* xf4  = g_xf4  + (size_t)n * 16 + d * 4;
        float4* agg4 = g_agg4 + (size_t)n * 16 + d * 4;
        float4* xrow = (float4*)(xs + nl * XSTR) + d * 4;
#pragma unroll
        for (int g4 = 0; g4 < 4; ++g4) {
            xf4[g4]  = o4[g4];
            xrow[g4] = o4[g4];
            agg4[g4] = make_float4(0.f, 0.f, 0.f, 0.f);
        }
    }
    __syncthreads();

    // ---- uv: ALL 256 threads, each computes 8 outputs for ONE node ----
    // thread t: part = t&3, nb = t>>2 (0..63).
    {
        int part = tid & 3;
        int nb   = tid >> 2;
        int n0 = nbase + nb;
        if (n0 < N) {
            const float4* xa4 = (const float4*)(xs + nb * XSTR);
            float acc[8];
#pragma unroll
            for (int q = 0; q < 8; ++q) acc[q] = 0.f;
#pragma unroll
            for (int k4 = 0; k4 < 16; ++k4) {
                float4 xa = xa4[k4];
#pragma unroll
                for (int q = 0; q < 8; ++q) {
                    const float4 wv = *(const float4*)(wt + (q * 4 + part) * XSTR + k4 * 4);
                    acc[q] += wv.x * xa.x + wv.y * xa.y + wv.z * xa.z + wv.w * xa.w;
                }
            }
            float4* uvp = (float4*)((float*)(g_uv4 + (size_t)n0 * 8) + part * 8);
            uvp[0] = make_float4(acc[0], acc[1], acc[2], acc[3]);
            uvp[1] = make_float4(acc[4], acc[5], acc[6], acc[7]);
        }
    }
}

// ---------------------------------------------------------------------------
// MGS QR of A = I + strictly-lower(params). Q[col][row].
// ---------------------------------------------------------------------------
__device__ __forceinline__ void qr4(const float p[6], float Q[4][4]) {
    const float a[4][4] = {
        {1.f,  p[0], p[1], p[3]},
        {0.f,  1.f,  p[2], p[4]},
        {0.f,  0.f,  1.f,  p[5]},
        {0.f,  0.f,  0.f,  1.f }};
#pragma unroll
    for (int c = 0; c < 4; ++c) {
        float v0 = a[c][0], v1 = a[c][1], v2 = a[c][2], v3 = a[c][3];
#pragma unroll
        for (int j = 0; j < c; ++j) {
            float r = v0 * Q[j][0] + v1 * Q[j][1] + v2 * Q[j][2] + v3 * Q[j][3];
            v0 -= r * Q[j][0];
            v1 -= r * Q[j][1];
            v2 -= r * Q[j][2];
            v3 -= r * Q[j][3];
        }
        float inv = rsqrtf(v0 * v0 + v1 * v1 + v2 * v2 + v3 * v3);
        Q[c][0] = v0 * inv; Q[c][1] = v1 * inv; Q[c][2] = v2 * inv; Q[c][3] = v3 * inv;
    }
}

__device__ __forceinline__ void red4(float4* addr, float4 v) {
    asm volatile("red.global.add.v4.f32 [%0], {%1, %2, %3, %4};"
                 :: "l"(addr), "f"(v.x), "f"(v.y), "f"(v.z), "f"(v.w)
                 : "memory");
}

// ---------------------------------------------------------------------------
// K2: phase-cooperative edge kernel (unchanged from round 11).
// ---------------------------------------------------------------------------
#define ROWS 36  // floats per edge row: 32 + pad; 144B = 16B-aligned, bank-clean

__global__ void __launch_bounds__(128, 8) k_edge(
        const int* __restrict__ ei,
        const float* __restrict__ b1,
        const float* __restrict__ w2,
        const float* __restrict__ b2,
        int E) {
    __shared__ __align__(16) float s_h[4][32 * ROWS];
    __shared__ float b1s[16];
    __shared__ float w2p[128];   // w2p[t*8+c], padded
    __shared__ float b2s[8];

    int tid = threadIdx.x;
    if (tid < 16) b1s[tid] = b1[tid];
    if (tid < 128) w2p[tid] = ((tid & 7) < 6) ? w2[(tid & 7) * 16 + (tid >> 3)] : 0.f;
    if (tid < 6)  b2s[tid] = b2[tid];
    __syncthreads();

    int lane = tid & 31;
    int w    = tid >> 5;
    float* Hs = s_h[w];

    int ebase = (blockIdx.x * 4 + w) * 32;
    int eg = ebase + lane;

    int rj = 0, ci = 0;
    if (eg < E) {
        rj = ei[eg];
        ci = ei[E + eg];
    }
    float s = rsqrtf((1.0f + g_deg[ci]) * (1.0f + g_deg[rj]));
    float b1r = b1s[lane & 15];

    // ---- Phase A: gather + fused relu-combine -> edge-major smem ----
    const float* uvbase = (const float*)g_uv4;
#pragma unroll 4
    for (int e = 0; e < 32; ++e) {
        int rje = __shfl_sync(0xffffffffu, rj, e);
        int cie = __shfl_sync(0xffffffffu, ci, e);
        float ui = __ldg(uvbase + (size_t)cie * 32 + lane);
        float uj = __ldg(uvbase + (size_t)rje * 32 + lane);
        float h = fmaxf(ui + __shfl_xor_sync(0xffffffffu, uj, 16) + b1r, 0.f);
        Hs[e * ROWS + lane] = h;
    }
    __syncwarp();

    // ---- Phase B: thread-per-edge mlp2 + QR + M ----
    {
        const float4* hrow = (const float4*)(Hs + lane * ROWS);
        float h_all[32];
#pragma unroll
        for (int q = 0; q < 8; ++q) {
            float4 v = hrow[q];
            h_all[q * 4 + 0] = v.x;
            h_all[q * 4 + 1] = v.y;
            h_all[q * 4 + 2] = v.z;
            h_all[q * 4 + 3] = v.w;
        }

        float pve[6], pue[6];
#pragma unroll
        for (int c = 0; c < 6; ++c) { pve[c] = b2s[c]; pue[c] = b2s[c]; }
#pragma unroll
        for (int t = 0; t < 16; ++t) {
            float4 wA = *(const float4*)(w2p + t * 8);
            float4 wB = *(const float4*)(w2p + t * 8 + 4);
            float hv = h_all[t];
            float hu = h_all[16 + t];
            pve[0] += wA.x * hv;  pue[0] += wA.x * hu;
            pve[1] += wA.y * hv;  pue[1] += wA.y * hu;
            pve[2] += wA.z * hv;  pue[2] += wA.z * hu;
            pve[3] += wA.w * hv;  pue[3] += wA.w * hu;
            pve[4] += wB.x * hv;  pue[4] += wB.x * hu;
            pve[5] += wB.y * hv;  pue[5] += wB.y * hu;
        }

        float Qv[4][4], Qu[4][4];
        qr4(pve, Qv);
        qr4(pue, Qu);

        float4* Mrow = (float4*)(Hs + lane * ROWS);
#pragma unroll
        for (int a = 0; a < 4; ++a) {
            float4 m;
            m.x = s * (Qv[a][0] * Qu[0][0] + Qv[a][1] * Qu[0][1] + Qv[a][2] * Qu[0][2] + Qv[a][3] * Qu[0][3]);
            m.y = s * (Qv[a][0] * Qu[1][0] + Qv[a][1] * Qu[1][1] + Qv[a][2] * Qu[1][2] + Qv[a][3] * Qu[1][3]);
            m.z = s * (Qv[a][0] * Qu[2][0] + Qv[a][1] * Qu[2][1] + Qv[a][2] * Qu[2][2] + Qv[a][3] * Qu[2][3]);
            m.w = s * (Qv[a][0] * Qu[3][0] + Qv[a][1] * Qu[3][1] + Qv[a][2] * Qu[3][2] + Qv[a][3] * Qu[3][3]);
            Mrow[a] = m;
        }
    }
    __syncwarp();

    // ---- Phase C: 16 lanes per edge, 2 edges per step ----
    int half = lane >> 4;
    int sub  = lane & 15;
    int a    = sub >> 2;
    int h4   = sub & 3;

#pragma unroll 4
    for (int it = 0; it < 16; ++it) {
        int e = it * 2 + half;
        int rje = __shfl_sync(0xffffffffu, rj, e);
        int cie = __shfl_sync(0xffffffffu, ci, e);

        const float4* xj4 = g_xf4 + (size_t)rje * 16;
        float4 x0 = __ldg(xj4 + 0 * 4 + h4);
        float4 x1 = __ldg(xj4 + 1 * 4 + h4);
        float4 x2 = __ldg(xj4 + 2 * 4 + h4);
        float4 x3 = __ldg(xj4 + 3 * 4 + h4);

        float4 mr = *(const float4*)(Hs + e * ROWS + a * 4);

        float4 m;
        m.x = mr.x * x0.x + mr.y * x1.x + mr.z * x2.x + mr.w * x3.x;
        m.y = mr.x * x0.y + mr.y * x1.y + mr.z * x2.y + mr.w * x3.y;
        m.z = mr.x * x0.z + mr.y * x1.z + mr.z * x2.z + mr.w * x3.z;
        m.w = mr.x * x0.w + mr.y * x1.w + mr.z * x2.w + mr.w * x3.w;

        if (ebase + e < E)
            red4(g_agg4 + (size_t)cie * 16 + a * 4 + h4, m);
    }
}

// ---------------------------------------------------------------------------
// K3: out = (1 + tanh(eps_d)) * x - elu(agg + xf/(1+deg)); resets deg -> 0.
// ---------------------------------------------------------------------------
__global__ void k_final(const float* __restrict__ x,
                        const float* __restrict__ eps,
                        float* __restrict__ out, int N) {
    int i = blockIdx.x * blockDim.x + threadIdx.x;   // float4 index
    if (i >= N * 16) return;
    int n = i >> 4;
    int d = (i >> 2) & 3;
    float coeff = 1.0f + tanhf(__ldg(eps + d));
    float degv = g_deg[n];
    float ds2 = 1.0f / (1.0f + degv);

    float4 ag = g_agg4[i];
    float4 xf = g_xf4[i];
    float4 xv = ((const float4*)x)[i];

    float a0 = ag.x + ds2 * xf.x;
    float a1 = ag.y + ds2 * xf.y;
    float a2 = ag.z + ds2 * xf.z;
    float a3 = ag.w + ds2 * xf.w;

    float4 o;
    o.x = coeff * xv.x - (a0 > 0.f ? a0 : expm1f(a0));
    o.y = coeff * xv.y - (a1 > 0.f ? a1 : expm1f(a1));
    o.z = coeff * xv.z - (a2 > 0.f ? a2 : expm1f(a2));
    o.w = coeff * xv.w - (a3 > 0.f ? a3 : expm1f(a3));
    ((float4*)out)[i] = o;

    if ((i & 15) == 0) g_deg[n] = 0.f;   // reset for next graph replay
}

// ---------------------------------------------------------------------------
extern "C" void kernel_launch(void* const* d_in, const int* in_sizes, int n_in,
                              void* d_out, int out_size) {
    const float* x   = (const float*)d_in[0];
    const int*   ei  = (const int*)d_in[1];   // int32 (JAX x64 disabled)
    const float* W1  = (const float*)d_in[2];
    const float* W2  = (const float*)d_in[3];
    const float* eps = (const float*)d_in[4];
    const float* m1w = (const float*)d_in[5];
    const float* m1b = (const float*)d_in[6];
    const float* m2w = (const float*)d_in[7];
    const float* m2b = (const float*)d_in[8];

    int N = in_sizes[0] / DH;
    int E = in_sizes[1] / 2;

    int TB = (N + 63) / 64;          // transform blocks (64 nodes each)
    int DB = (E + 255) / 256;        // degree blocks

    k_transform_deg_uv<<<TB + DB, 256>>>(x, W1, W2, m1w, ei, N, E, TB);
    k_edge<<<(E + 127) / 128, 128>>>(ei, m1b, m2w, m2b, E);
    k_final<<<(N * 16 + 255) / 256, 256>>>(x, eps, (float*)d_out, N);
}

// round 13
// speedup vs baseline: 1.0741x; 1.0741x over previous
#include <cuda_runtime.h>
#include <math.h>

#define D 4
#define H 16
#define DH 64

#define N_MAX 65536

// Scratch (device globals). 256B alignment -> whole 128B lines per node.
__device__ __align__(256) float4 g_xf4[N_MAX * (DH / 4)];    // transformed features
__device__ __align__(256) float4 g_uv4[N_MAX * 8];           // per-node u(16), v(16)
__device__ __align__(256) float4 g_agg4[N_MAX * (DH / 4)];   // message aggregation
__device__ float  g_deg[N_MAX];   // starts 0; K1 accumulates; k_final resets to 0

// ---------------------------------------------------------------------------
// K1 (fused): blocks [0, TB): node transform + u/v projection (smem-staged);
// blocks [TB, TB+DB): source-node out-degree atomics.  (round-11 winner)
// ---------------------------------------------------------------------------
#define XSTR 68   // padded node row stride (floats): float4-aligned, conflict-free

__global__ void __launch_bounds__(256) k_transform_deg_uv(
        const float* __restrict__ x,
        const float* __restrict__ W1,
        const float* __restrict__ W2,
        const float* __restrict__ m1w,
        const int* __restrict__ ei,
        int N, int E, int TB) {
    __shared__ float W1s[16];
    __shared__ __align__(16) float W2s[256];
    __shared__ __align__(16) float xs[64 * XSTR];   // 64 nodes staged / xf overwrite
    // uv weights at row (q*4 + part): part-stride 68 = 4 (mod 32) -> conflict-free.
    __shared__ __align__(16) float wt[32 * XSTR];

    int tid = threadIdx.x;

    if (blockIdx.x >= TB) {
        int e = (blockIdx.x - TB) * 256 + tid;
        if (e < E) atomicAdd(&g_deg[ei[e]], 1.0f);
        return;
    }

    if (tid < 16) W1s[tid] = W1[tid];
    for (int i = tid; i < 256; i += 256) W2s[i] = W2[i];
    for (int i = tid; i < 32 * 64; i += 256) {
        int oi = i >> 6;
        int k  = i & 63;
        int part = oi >> 3;
        int q    = oi & 7;
        float wv = (oi < 16) ? m1w[oi * 128 + k]
                             : m1w[(oi - 16) * 128 + 64 + k];
        wt[(q * 4 + part) * XSTR + k] = wv;
    }

    int nbase = blockIdx.x * 64;
    int navail = N - nbase;
    int nloc = navail >= 64 ? 64 : navail;
    int total = nloc * 64;
#pragma unroll 4
    for (int i = tid; i < total; i += 256) {
        int nl = i >> 6;
        int k  = i & 63;
        xs[nl * XSTR + k] = x[(size_t)nbase * 64 + i];
    }
    __syncthreads();

    int nl = tid >> 2;           // local node 0..63
    int d  = tid & 3;
    int n  = nbase + nl;

    float4 o4[4];
    if (n < N) {
        const float* xr = xs + nl * XSTR;
        float tf[16];
#pragma unroll
        for (int f = 0; f < 16; ++f) tf[f] = 0.f;
#pragma unroll
        for (int dd = 0; dd < 4; ++dd) {
            float w = W1s[dd * 4 + d];
#pragma unroll
            for (int f = 0; f < 16; ++f) tf[f] += w * xr[dd * 16 + f];
        }
        const float4* W2s4 = (const float4*)W2s;
#pragma unroll
        for (int g4 = 0; g4 < 4; ++g4) o4[g4] = make_float4(0.f, 0.f, 0.f, 0.f);
#pragma unroll
        for (int f = 0; f < 16; ++f) {
            float tv = tf[f];
#pragma unroll
            for (int g4 = 0; g4 < 4; ++g4) {
                float4 wv = W2s4[f * 4 + g4];
                o4[g4].x += tv * wv.x;
                o4[g4].y += tv * wv.y;
                o4[g4].z += tv * wv.z;
                o4[g4].w += tv * wv.w;
            }
        }
    }
    __syncthreads();   // all xs reads done before overwrite

    if (n < N) {
        float4* xf4  = g_xf4  + (size_t)n * 16 + d * 4;
        float4* agg4 = g_agg4 + (size_t)n * 16 + d * 4;
        float4* xrow = (float4*)(xs + nl * XSTR) + d * 4;
#pragma unroll
        for (int g4 = 0; g4 < 4; ++g4) {
            xf4[g4]  = o4[g4];
            xrow[g4] = o4[g4];
            agg4[g4] = make_float4(0.f, 0.f, 0.f, 0.f);
        }
    }
    __syncthreads();

    // ---- uv: 128 threads, each computes 8 outputs for TWO nodes ----
    if (tid < 128) {
        int part = tid & 3;
        int nb   = tid >> 2;
        int n0 = nbase + nb;
        int n1 = nbase + nb + 32;
        bool v0 = (n0 < N);
        bool v1 = (n1 < N);

        const float4* xa4 = (const float4*)(xs + nb * XSTR);
        const float4* xb4 = (const float4*)(xs + (nb + 32) * XSTR);

        float acc0[8], acc1[8];
#pragma unroll
        for (int q = 0; q < 8; ++q) { acc0[q] = 0.f; acc1[q] = 0.f; }

#pragma unroll
        for (int k4 = 0; k4 < 16; ++k4) {
            float4 xa = v0 ? xa4[k4] : make_float4(0.f, 0.f, 0.f, 0.f);
            float4 xb = v1 ? xb4[k4] : make_float4(0.f, 0.f, 0.f, 0.f);
#pragma unroll
            for (int q = 0; q < 8; ++q) {
                const float4 wv = *(const float4*)(wt + (q * 4 + part) * XSTR + k4 * 4);
                acc0[q] += wv.x * xa.x + wv.y * xa.y + wv.z * xa.z + wv.w * xa.w;
                acc1[q] += wv.x * xb.x + wv.y * xb.y + wv.z * xb.z + wv.w * xb.w;
            }
        }
        if (v0) {
            float4* uvp = (float4*)((float*)(g_uv4 + (size_t)n0 * 8) + part * 8);
            uvp[0] = make_float4(acc0[0], acc0[1], acc0[2], acc0[3]);
            uvp[1] = make_float4(acc0[4], acc0[5], acc0[6], acc0[7]);
        }
        if (v1) {
            float4* uvp = (float4*)((float*)(g_uv4 + (size_t)n1 * 8) + part * 8);
            uvp[0] = make_float4(acc1[0], acc1[1], acc1[2], acc1[3]);
            uvp[1] = make_float4(acc1[4], acc1[5], acc1[6], acc1[7]);
        }
    }
}

// ---------------------------------------------------------------------------
// MGS QR of A = I + strictly-lower(params). Q[col][row].
// ---------------------------------------------------------------------------
__device__ __forceinline__ void qr4(const float p[6], float Q[4][4]) {
    const float a[4][4] = {
        {1.f,  p[0], p[1], p[3]},
        {0.f,  1.f,  p[2], p[4]},
        {0.f,  0.f,  1.f,  p[5]},
        {0.f,  0.f,  0.f,  1.f }};
#pragma unroll
    for (int c = 0; c < 4; ++c) {
        float v0 = a[c][0], v1 = a[c][1], v2 = a[c][2], v3 = a[c][3];
#pragma unroll
        for (int j = 0; j < c; ++j) {
            float r = v0 * Q[j][0] + v1 * Q[j][1] + v2 * Q[j][2] + v3 * Q[j][3];
            v0 -= r * Q[j][0];
            v1 -= r * Q[j][1];
            v2 -= r * Q[j][2];
            v3 -= r * Q[j][3];
        }
        float inv = rsqrtf(v0 * v0 + v1 * v1 + v2 * v2 + v3 * v3);
        Q[c][0] = v0 * inv; Q[c][1] = v1 * inv; Q[c][2] = v2 * inv; Q[c][3] = v3 * inv;
    }
}

__device__ __forceinline__ void red4(float4* addr, float4 v) {
    asm volatile("red.global.add.v4.f32 [%0], {%1, %2, %3, %4};"
                 :: "l"(addr), "f"(v.x), "f"(v.y), "f"(v.z), "f"(v.w)
                 : "memory");
}

// ---------------------------------------------------------------------------
// K2: phase-cooperative edge kernel. Phase A reworked: 8 lanes per edge,
// float4 uv quarters, u<->v pairing via shfl_xor(lane,4). Fewer issue slots,
// same L1 wavefronts. Phases B/C unchanged.
// ---------------------------------------------------------------------------
#define ROWS 36  // floats per edge row: 32 + pad; 144B = 16B-aligned, bank-clean

__global__ void __launch_bounds__(128, 8) k_edge(
        const int* __restrict__ ei,
        const float* __restrict__ b1,
        const float* __restrict__ w2,
        const float* __restrict__ b2,
        int E) {
    __shared__ __align__(16) float s_h[4][32 * ROWS];
    __shared__ __align__(16) float b1s[16];
    __shared__ float w2p[128];   // w2p[t*8+c], padded
    __shared__ float b2s[8];

    int tid = threadIdx.x;
    if (tid < 16) b1s[tid] = b1[tid];
    if (tid < 128) w2p[tid] = ((tid & 7) < 6) ? w2[(tid & 7) * 16 + (tid >> 3)] : 0.f;
    if (tid < 6)  b2s[tid] = b2[tid];
    __syncthreads();

    int lane = tid & 31;
    int w    = tid >> 5;
    float* Hs = s_h[w];

    int ebase = (blockIdx.x * 4 + w) * 32;
    int eg = ebase + lane;

    int rj = 0, ci = 0;
    if (eg < E) {
        rj = ei[eg];
        ci = ei[E + eg];
    }
    float s = rsqrtf((1.0f + g_deg[ci]) * (1.0f + g_deg[rj]));

    // ---- Phase A: 8 lanes per edge, float4 quarters, fused relu-combine ----
    // lane sub<4 owns u quarter sub; sub>=4 owns v quarter (sub-4).
    // h row entry: sub<4 -> hve[4sub..], sub>=4 -> hue[4(sub-4)..].
    {
        const float4* uv4base = (const float4*)g_uv4;
        int sub = lane & 7;
        int esl = lane >> 3;                       // 0..3: edge slot per iter
        float4 b1v = ((const float4*)b1s)[sub & 3];
#pragma unroll
        for (int g = 0; g < 8; ++g) {
            int eid = g * 4 + esl;
            int rje = __shfl_sync(0xffffffffu, rj, eid);
            int cie = __shfl_sync(0xffffffffu, ci, eid);
            float4 ui4 = __ldg(uv4base + (size_t)cie * 8 + sub);
            float4 uj4 = __ldg(uv4base + (size_t)rje * 8 + sub);
            float4 oj;
            oj.x = __shfl_xor_sync(0xffffffffu, uj4.x, 4);
            oj.y = __shfl_xor_sync(0xffffffffu, uj4.y, 4);
            oj.z = __shfl_xor_sync(0xffffffffu, uj4.z, 4);
            oj.w = __shfl_xor_sync(0xffffffffu, uj4.w, 4);
            float4 h;
            h.x = fmaxf(ui4.x + oj.x + b1v.x, 0.f);
            h.y = fmaxf(ui4.y + oj.y + b1v.y, 0.f);
            h.z = fmaxf(ui4.z + oj.z + b1v.z, 0.f);
            h.w = fmaxf(ui4.w + oj.w + b1v.w, 0.f);
            ((float4*)(Hs + eid * ROWS))[sub] = h;
        }
    }
    __syncwarp();

    // ---- Phase B: thread-per-edge mlp2 + QR + M ----
    {
        const float4* hrow = (const float4*)(Hs + lane * ROWS);
        float h_all[32];
#pragma unroll
        for (int q = 0; q < 8; ++q) {
            float4 v = hrow[q];
            h_all[q * 4 + 0] = v.x;
            h_all[q * 4 + 1] = v.y;
            h_all[q * 4 + 2] = v.z;
            h_all[q * 4 + 3] = v.w;
        }

        float pve[6], pue[6];
#pragma unroll
        for (int c = 0; c < 6; ++c) { pve[c] = b2s[c]; pue[c] = b2s[c]; }
#pragma unroll
        for (int t = 0; t < 16; ++t) {
            float4 wA = *(const float4*)(w2p + t * 8);
            float4 wB = *(const float4*)(w2p + t * 8 + 4);
            float hv = h_all[t];
            float hu = h_all[16 + t];
            pve[0] += wA.x * hv;  pue[0] += wA.x * hu;
            pve[1] += wA.y * hv;  pue[1] += wA.y * hu;
            pve[2] += wA.z * hv;  pue[2] += wA.z * hu;
            pve[3] += wA.w * hv;  pue[3] += wA.w * hu;
            pve[4] += wB.x * hv;  pue[4] += wB.x * hu;
            pve[5] += wB.y * hv;  pue[5] += wB.y * hu;
        }

        float Qv[4][4], Qu[4][4];
        qr4(pve, Qv);
        qr4(pue, Qu);

        float4* Mrow = (float4*)(Hs + lane * ROWS);
#pragma unroll
        for (int a = 0; a < 4; ++a) {
            float4 m;
            m.x = s * (Qv[a][0] * Qu[0][0] + Qv[a][1] * Qu[0][1] + Qv[a][2] * Qu[0][2] + Qv[a][3] * Qu[0][3]);
            m.y = s * (Qv[a][0] * Qu[1][0] + Qv[a][1] * Qu[1][1] + Qv[a][2] * Qu[1][2] + Qv[a][3] * Qu[1][3]);
            m.z = s * (Qv[a][0] * Qu[2][0] + Qv[a][1] * Qu[2][1] + Qv[a][2] * Qu[2][2] + Qv[a][3] * Qu[2][3]);
            m.w = s * (Qv[a][0] * Qu[3][0] + Qv[a][1] * Qu[3][1] + Qv[a][2] * Qu[3][2] + Qv[a][3] * Qu[3][3]);
            Mrow[a] = m;
        }
    }
    __syncwarp();

    // ---- Phase C: 16 lanes per edge, 2 edges per step ----
    int half = lane >> 4;
    int sub  = lane & 15;
    int a    = sub >> 2;
    int h4   = sub & 3;

#pragma unroll 4
    for (int it = 0; it < 16; ++it) {
        int e = it * 2 + half;
        int rje = __shfl_sync(0xffffffffu, rj, e);
        int cie = __shfl_sync(0xffffffffu, ci, e);

        const float4* xj4 = g_xf4 + (size_t)rje * 16;
        float4 x0 = __ldg(xj4 + 0 * 4 + h4);
        float4 x1 = __ldg(xj4 + 1 * 4 + h4);
        float4 x2 = __ldg(xj4 + 2 * 4 + h4);
        float4 x3 = __ldg(xj4 + 3 * 4 + h4);

        float4 mr = *(const float4*)(Hs + e * ROWS + a * 4);

        float4 m;
        m.x = mr.x * x0.x + mr.y * x1.x + mr.z * x2.x + mr.w * x3.x;
        m.y = mr.x * x0.y + mr.y * x1.y + mr.z * x2.y + mr.w * x3.y;
        m.z = mr.x * x0.z + mr.y * x1.z + mr.z * x2.z + mr.w * x3.z;
        m.w = mr.x * x0.w + mr.y * x1.w + mr.z * x2.w + mr.w * x3.w;

        if (ebase + e < E)
            red4(g_agg4 + (size_t)cie * 16 + a * 4 + h4, m);
    }
}

// ---------------------------------------------------------------------------
// K3: out = (1 + tanh(eps_d)) * x - elu(agg + xf/(1+deg)); resets deg -> 0.
// ---------------------------------------------------------------------------
__global__ void k_final(const float* __restrict__ x,
                        const float* __restrict__ eps,
                        float* __restrict__ out, int N) {
    int i = blockIdx.x * blockDim.x + threadIdx.x;   // float4 index
    if (i >= N * 16) return;
    int n = i >> 4;
    int d = (i >> 2) & 3;
    float coeff = 1.0f + tanhf(__ldg(eps + d));
    float degv = g_deg[n];
    float ds2 = 1.0f / (1.0f + degv);

    float4 ag = g_agg4[i];
    float4 xf = g_xf4[i];
    float4 xv = ((const float4*)x)[i];

    float a0 = ag.x + ds2 * xf.x;
    float a1 = ag.y + ds2 * xf.y;
    float a2 = ag.z + ds2 * xf.z;
    float a3 = ag.w + ds2 * xf.w;

    float4 o;
    o.x = coeff * xv.x - (a0 > 0.f ? a0 : expm1f(a0));
    o.y = coeff * xv.y - (a1 > 0.f ? a1 : expm1f(a1));
    o.z = coeff * xv.z - (a2 > 0.f ? a2 : expm1f(a2));
    o.w = coeff * xv.w - (a3 > 0.f ? a3 : expm1f(a3));
    ((float4*)out)[i] = o;

    if ((i & 15) == 0) g_deg[n] = 0.f;   // reset for next graph replay
}

// ---------------------------------------------------------------------------
extern "C" void kernel_launch(void* const* d_in, const int* in_sizes, int n_in,
                              void* d_out, int out_size) {
    const float* x   = (const float*)d_in[0];
    const int*   ei  = (const int*)d_in[1];   // int32 (JAX x64 disabled)
    const float* W1  = (const float*)d_in[2];
    const float* W2  = (const float*)d_in[3];
    const float* eps = (const float*)d_in[4];
    const float* m1w = (const float*)d_in[5];
    const float* m1b = (const float*)d_in[6];
    const float* m2w = (const float*)d_in[7];
    const float* m2b = (const float*)d_in[8];

    int N = in_sizes[0] / DH;
    int E = in_sizes[1] / 2;

    int TB = (N + 63) / 64;          // transform blocks (64 nodes each)
    int DB = (E + 255) / 256;        // degree blocks

    k_transform_deg_uv<<<TB + DB, 256>>>(x, W1, W2, m1w, ei, N, E, TB);
    k_edge<<<(E + 127) / 128, 128>>>(ei, m1b, m2w, m2b, E);
    k_final<<<(N * 16 + 255) / 256, 256>>>(x, eps, (float*)d_out, N);
}

// round 14
// speedup vs baseline: 1.0748x; 1.0006x over previous
#include <cuda_runtime.h>
#include <math.h>

#define D 4
#define H 16
#define DH 64

#define N_MAX 65536

// Scratch (device globals). 256B alignment -> whole 128B lines per node.
__device__ __align__(256) float4 g_xf4[N_MAX * (DH / 4)];    // transformed features
__device__ __align__(256) float4 g_uv4[N_MAX * 8];           // per-node u(16), v(16)
__device__ __align__(256) float4 g_agg4[N_MAX * (DH / 4)];   // message aggregation
__device__ float  g_deg[N_MAX];   // starts 0; K1 accumulates; k_final resets to 0

// ---------------------------------------------------------------------------
// K1 (fused): blocks [0, TB): node transform + u/v projection (smem-staged);
// blocks [TB, TB+DB): grid-strided source-node out-degree atomics.
// tf fused into o-accumulation (scalar tf) -> fewer live regs -> 5 blocks/SM.
// ---------------------------------------------------------------------------
#define XSTR 68   // padded node row stride (floats): float4-aligned, conflict-free

__global__ void __launch_bounds__(256, 5) k_transform_deg_uv(
        const float* __restrict__ x,
        const float* __restrict__ W1,
        const float* __restrict__ W2,
        const float* __restrict__ m1w,
        const int* __restrict__ ei,
        int N, int E, int TB, int DB) {
    __shared__ float W1s[16];
    __shared__ __align__(16) float W2s[256];
    __shared__ __align__(16) float xs[64 * XSTR];   // 64 nodes staged / xf overwrite
    // uv weights at row (q*4 + part): part-stride 68 = 4 (mod 32) -> conflict-free.
    __shared__ __align__(16) float wt[32 * XSTR];

    int tid = threadIdx.x;

    if (blockIdx.x >= TB) {
        // ---- degree part: grid-strided over DB persistent blocks ----
        int base   = (blockIdx.x - TB) * 256 + tid;
        int stride = DB * 256;
        for (int e = base; e < E; e += stride)
            atomicAdd(&g_deg[ei[e]], 1.0f);
        return;
    }

    if (tid < 16) W1s[tid] = W1[tid];
    for (int i = tid; i < 256; i += 256) W2s[i] = W2[i];
    for (int i = tid; i < 32 * 64; i += 256) {
        int oi = i >> 6;
        int k  = i & 63;
        int part = oi >> 3;
        int q    = oi & 7;
        float wv = (oi < 16) ? m1w[oi * 128 + k]
                             : m1w[(oi - 16) * 128 + 64 + k];
        wt[(q * 4 + part) * XSTR + k] = wv;
    }

    int nbase = blockIdx.x * 64;
    int navail = N - nbase;
    int nloc = navail >= 64 ? 64 : navail;
    int total = nloc * 64;
#pragma unroll 4
    for (int i = tid; i < total; i += 256) {
        int nl = i >> 6;
        int k  = i & 63;
        xs[nl * XSTR + k] = x[(size_t)nbase * 64 + i];
    }
    __syncthreads();

    int nl = tid >> 2;           // local node 0..63
    int d  = tid & 3;
    int n  = nbase + nl;

    float4 o4[4];
    if (n < N) {
        const float* xr = xs + nl * XSTR;
        const float4* W2s4 = (const float4*)W2s;
        float w0 = W1s[d], w1 = W1s[4 + d], w2w = W1s[8 + d], w3 = W1s[12 + d];
#pragma unroll
        for (int g4 = 0; g4 < 4; ++g4) o4[g4] = make_float4(0.f, 0.f, 0.f, 0.f);
#pragma unroll
        for (int f = 0; f < 16; ++f) {
            // same accumulation order as before: dd ascending, then f ascending
            float tf = w0 * xr[f];
            tf += w1 * xr[16 + f];
            tf += w2w * xr[32 + f];
            tf += w3 * xr[48 + f];
#pragma unroll
            for (int g4 = 0; g4 < 4; ++g4) {
                float4 wv = W2s4[f * 4 + g4];
                o4[g4].x += tf * wv.x;
                o4[g4].y += tf * wv.y;
                o4[g4].z += tf * wv.z;
                o4[g4].w += tf * wv.w;
            }
        }
    }
    __syncthreads();   // all xs reads done before overwrite

    if (n < N) {
        float4* xf4  = g_xf4  + (size_t)n * 16 + d * 4;
        float4* agg4 = g_agg4 + (size_t)n * 16 + d * 4;
        float4* xrow = (float4*)(xs + nl * XSTR) + d * 4;
#pragma unroll
        for (int g4 = 0; g4 < 4; ++g4) {
            xf4[g4]  = o4[g4];
            xrow[g4] = o4[g4];
            agg4[g4] = make_float4(0.f, 0.f, 0.f, 0.f);
        }
    }
    __syncthreads();

    // ---- uv: 128 threads, each computes 8 outputs for TWO nodes ----
    if (tid < 128) {
        int part = tid & 3;
        int nb   = tid >> 2;
        int n0 = nbase + nb;
        int n1 = nbase + nb + 32;
        bool v0 = (n0 < N);
        bool v1 = (n1 < N);

        const float4* xa4 = (const float4*)(xs + nb * XSTR);
        const float4* xb4 = (const float4*)(xs + (nb + 32) * XSTR);

        float acc0[8], acc1[8];
#pragma unroll
        for (int q = 0; q < 8; ++q) { acc0[q] = 0.f; acc1[q] = 0.f; }

#pragma unroll
        for (int k4 = 0; k4 < 16; ++k4) {
            float4 xa = v0 ? xa4[k4] : make_float4(0.f, 0.f, 0.f, 0.f);
            float4 xb = v1 ? xb4[k4] : make_float4(0.f, 0.f, 0.f, 0.f);
#pragma unroll
            for (int q = 0; q < 8; ++q) {
                const float4 wv = *(const float4*)(wt + (q * 4 + part) * XSTR + k4 * 4);
                acc0[q] += wv.x * xa.x + wv.y * xa.y + wv.z * xa.z + wv.w * xa.w;
                acc1[q] += wv.x * xb.x + wv.y * xb.y + wv.z * xb.z + wv.w * xb.w;
            }
        }
        if (v0) {
            float4* uvp = (float4*)((float*)(g_uv4 + (size_t)n0 * 8) + part * 8);
            uvp[0] = make_float4(acc0[0], acc0[1], acc0[2], acc0[3]);
            uvp[1] = make_float4(acc0[4], acc0[5], acc0[6], acc0[7]);
        }
        if (v1) {
            float4* uvp = (float4*)((float*)(g_uv4 + (size_t)n1 * 8) + part * 8);
            uvp[0] = make_float4(acc1[0], acc1[1], acc1[2], acc1[3]);
            uvp[1] = make_float4(acc1[4], acc1[5], acc1[6], acc1[7]);
        }
    }
}

// ---------------------------------------------------------------------------
// MGS QR of A = I + strictly-lower(params). Q[col][row].
// ---------------------------------------------------------------------------
__device__ __forceinline__ void qr4(const float p[6], float Q[4][4]) {
    const float a[4][4] = {
        {1.f,  p[0], p[1], p[3]},
        {0.f,  1.f,  p[2], p[4]},
        {0.f,  0.f,  1.f,  p[5]},
        {0.f,  0.f,  0.f,  1.f }};
#pragma unroll
    for (int c = 0; c < 4; ++c) {
        float v0 = a[c][0], v1 = a[c][1], v2 = a[c][2], v3 = a[c][3];
#pragma unroll
        for (int j = 0; j < c; ++j) {
            float r = v0 * Q[j][0] + v1 * Q[j][1] + v2 * Q[j][2] + v3 * Q[j][3];
            v0 -= r * Q[j][0];
            v1 -= r * Q[j][1];
            v2 -= r * Q[j][2];
            v3 -= r * Q[j][3];
        }
        float inv = rsqrtf(v0 * v0 + v1 * v1 + v2 * v2 + v3 * v3);
        Q[c][0] = v0 * inv; Q[c][1] = v1 * inv; Q[c][2] = v2 * inv; Q[c][3] = v3 * inv;
    }
}

__device__ __forceinline__ void red4(float4* addr, float4 v) {
    asm volatile("red.global.add.v4.f32 [%0], {%1, %2, %3, %4};"
                 :: "l"(addr), "f"(v.x), "f"(v.y), "f"(v.z), "f"(v.w)
                 : "memory");
}

// ---------------------------------------------------------------------------
// K2: phase-cooperative edge kernel (round-13 winner, unchanged).
// ---------------------------------------------------------------------------
#define ROWS 36  // floats per edge row: 32 + pad; 144B = 16B-aligned, bank-clean

__global__ void __launch_bounds__(128, 8) k_edge(
        const int* __restrict__ ei,
        const float* __restrict__ b1,
        const float* __restrict__ w2,
        const float* __restrict__ b2,
        int E) {
    __shared__ __align__(16) float s_h[4][32 * ROWS];
    __shared__ __align__(16) float b1s[16];
    __shared__ float w2p[128];   // w2p[t*8+c], padded
    __shared__ float b2s[8];

    int tid = threadIdx.x;
    if (tid < 16) b1s[tid] = b1[tid];
    if (tid < 128) w2p[tid] = ((tid & 7) < 6) ? w2[(tid & 7) * 16 + (tid >> 3)] : 0.f;
    if (tid < 6)  b2s[tid] = b2[tid];
    __syncthreads();

    int lane = tid & 31;
    int w    = tid >> 5;
    float* Hs = s_h[w];

    int ebase = (blockIdx.x * 4 + w) * 32;
    int eg = ebase + lane;

    int rj = 0, ci = 0;
    if (eg < E) {
        rj = ei[eg];
        ci = ei[E + eg];
    }
    float s = rsqrtf((1.0f + g_deg[ci]) * (1.0f + g_deg[rj]));

    // ---- Phase A: 8 lanes per edge, float4 quarters, fused relu-combine ----
    {
        const float4* uv4base = (const float4*)g_uv4;
        int sub = lane & 7;
        int esl = lane >> 3;                       // 0..3: edge slot per iter
        float4 b1v = ((const float4*)b1s)[sub & 3];
#pragma unroll
        for (int g = 0; g < 8; ++g) {
            int eid = g * 4 + esl;
            int rje = __shfl_sync(0xffffffffu, rj, eid);
            int cie = __shfl_sync(0xffffffffu, ci, eid);
            float4 ui4 = __ldg(uv4base + (size_t)cie * 8 + sub);
            float4 uj4 = __ldg(uv4base + (size_t)rje * 8 + sub);
            float4 oj;
            oj.x = __shfl_xor_sync(0xffffffffu, uj4.x, 4);
            oj.y = __shfl_xor_sync(0xffffffffu, uj4.y, 4);
            oj.z = __shfl_xor_sync(0xffffffffu, uj4.z, 4);
            oj.w = __shfl_xor_sync(0xffffffffu, uj4.w, 4);
            float4 h;
            h.x = fmaxf(ui4.x + oj.x + b1v.x, 0.f);
            h.y = fmaxf(ui4.y + oj.y + b1v.y, 0.f);
            h.z = fmaxf(ui4.z + oj.z + b1v.z, 0.f);
            h.w = fmaxf(ui4.w + oj.w + b1v.w, 0.f);
            ((float4*)(Hs + eid * ROWS))[sub] = h;
        }
    }
    __syncwarp();

    // ---- Phase B: thread-per-edge mlp2 + QR + M ----
    {
        const float4* hrow = (const float4*)(Hs + lane * ROWS);
        float h_all[32];
#pragma unroll
        for (int q = 0; q < 8; ++q) {
            float4 v = hrow[q];
            h_all[q * 4 + 0] = v.x;
            h_all[q * 4 + 1] = v.y;
            h_all[q * 4 + 2] = v.z;
            h_all[q * 4 + 3] = v.w;
        }

        float pve[6], pue[6];
#pragma unroll
        for (int c = 0; c < 6; ++c) { pve[c] = b2s[c]; pue[c] = b2s[c]; }
#pragma unroll
        for (int t = 0; t < 16; ++t) {
            float4 wA = *(const float4*)(w2p + t * 8);
            float4 wB = *(const float4*)(w2p + t * 8 + 4);
            float hv = h_all[t];
            float hu = h_all[16 + t];
            pve[0] += wA.x * hv;  pue[0] += wA.x * hu;
            pve[1] += wA.y * hv;  pue[1] += wA.y * hu;
            pve[2] += wA.z * hv;  pue[2] += wA.z * hu;
            pve[3] += wA.w * hv;  pue[3] += wA.w * hu;
            pve[4] += wB.x * hv;  pue[4] += wB.x * hu;
            pve[5] += wB.y * hv;  pue[5] += wB.y * hu;
        }

        float Qv[4][4], Qu[4][4];
        qr4(pve, Qv);
        qr4(pue, Qu);

        float4* Mrow = (float4*)(Hs + lane * ROWS);
#pragma unroll
        for (int a = 0; a < 4; ++a) {
            float4 m;
            m.x = s * (Qv[a][0] * Qu[0][0] + Qv[a][1] * Qu[0][1] + Qv[a][2] * Qu[0][2] + Qv[a][3] * Qu[0][3]);
            m.y = s * (Qv[a][0] * Qu[1][0] + Qv[a][1] * Qu[1][1] + Qv[a][2] * Qu[1][2] + Qv[a][3] * Qu[1][3]);
            m.z = s * (Qv[a][0] * Qu[2][0] + Qv[a][1] * Qu[2][1] + Qv[a][2] * Qu[2][2] + Qv[a][3] * Qu[2][3]);
            m.w = s * (Qv[a][0] * Qu[3][0] + Qv[a][1] * Qu[3][1] + Qv[a][2] * Qu[3][2] + Qv[a][3] * Qu[3][3]);
            Mrow[a] = m;
        }
    }
    __syncwarp();

    // ---- Phase C: 16 lanes per edge, 2 edges per step ----
    int half = lane >> 4;
    int sub  = lane & 15;
    int a    = sub >> 2;
    int h4   = sub & 3;

#pragma unroll 4
    for (int it = 0; it < 16; ++it) {
        int e = it * 2 + half;
        int rje = __shfl_sync(0xffffffffu, rj, e);
        int cie = __shfl_sync(0xffffffffu, ci, e);

        const float4* xj4 = g_xf4 + (size_t)rje * 16;
        float4 x0 = __ldg(xj4 + 0 * 4 + h4);
        float4 x1 = __ldg(xj4 + 1 * 4 + h4);
        float4 x2 = __ldg(xj4 + 2 * 4 + h4);
        float4 x3 = __ldg(xj4 + 3 * 4 + h4);

        float4 mr = *(const float4*)(Hs + e * ROWS + a * 4);

        float4 m;
        m.x = mr.x * x0.x + mr.y * x1.x + mr.z * x2.x + mr.w * x3.x;
        m.y = mr.x * x0.y + mr.y * x1.y + mr.z * x2.y + mr.w * x3.y;
        m.z = mr.x * x0.z + mr.y * x1.z + mr.z * x2.z + mr.w * x3.z;
        m.w = mr.x * x0.w + mr.y * x1.w + mr.z * x2.w + mr.w * x3.w;

        if (ebase + e < E)
            red4(g_agg4 + (size_t)cie * 16 + a * 4 + h4, m);
    }
}

// ---------------------------------------------------------------------------
// K3: out = (1 + tanh(eps_d)) * x - elu(agg + xf/(1+deg)); resets deg -> 0.
// ---------------------------------------------------------------------------
__global__ void k_final(const float* __restrict__ x,
                        const float* __restrict__ eps,
                        float* __restrict__ out, int N) {
    int i = blockIdx.x * blockDim.x + threadIdx.x;   // float4 index
    if (i >= N * 16) return;
    int n = i >> 4;
    int d = (i >> 2) & 3;
    float coeff = 1.0f + tanhf(__ldg(eps + d));
    float degv = g_deg[n];
    float ds2 = 1.0f / (1.0f + degv);

    float4 ag = g_agg4[i];
    float4 xf = g_xf4[i];
    float4 xv = ((const float4*)x)[i];

    float a0 = ag.x + ds2 * xf.x;
    float a1 = ag.y + ds2 * xf.y;
    float a2 = ag.z + ds2 * xf.z;
    float a3 = ag.w + ds2 * xf.w;

    float4 o;
    o.x = coeff * xv.x - (a0 > 0.f ? a0 : expm1f(a0));
    o.y = coeff * xv.y - (a1 > 0.f ? a1 : expm1f(a1));
    o.z = coeff * xv.z - (a2 > 0.f ? a2 : expm1f(a2));
    o.w = coeff * xv.w - (a3 > 0.f ? a3 : expm1f(a3));
    ((float4*)out)[i] = o;

    if ((i & 15) == 0) g_deg[n] = 0.f;   // reset for next graph replay
}

// ---------------------------------------------------------------------------
extern "C" void kernel_launch(void* const* d_in, const int* in_sizes, int n_in,
                              void* d_out, int out_size) {
    const float* x   = (const float*)d_in[0];
    const int*   ei  = (const int*)d_in[1];   // int32 (JAX x64 disabled)
    const float* W1  = (const float*)d_in[2];
    const float* W2  = (const float*)d_in[3];
    const float* eps = (const float*)d_in[4];
    const float* m1w = (const float*)d_in[5];
    const float* m1b = (const float*)d_in[6];
    const float* m2w = (const float*)d_in[7];
    const float* m2b = (const float*)d_in[8];

    int N = in_sizes[0] / DH;
    int E = in_sizes[1] / 2;

    int TB = (N + 63) / 64;          // transform blocks (64 nodes each)
    int DB = 592;                    // persistent degree blocks (~4/SM)

    k_transform_deg_uv<<<TB + DB, 256>>>(x, W1, W2, m1w, ei, N, E, TB, DB);
    k_edge<<<(E + 127) / 128, 128>>>(ei, m1b, m2w, m2b, E);
    k_final<<<(N * 16 + 255) / 256, 256>>>(x, eps, (float*)d_out, N);
}

// round 15
// speedup vs baseline: 1.1150x; 1.0375x over previous
#include <cuda_runtime.h>
#include <math.h>

#define D 4
#define H 16
#define DH 64

#define N_MAX 65536

// Scratch (device globals). 256B alignment -> whole 128B lines per node.
__device__ __align__(256) float4 g_xf4[N_MAX * (DH / 4)];    // transformed features
__device__ __align__(256) float4 g_uv4[N_MAX * 8];           // per-node u(16), v(16)
__device__ __align__(256) float4 g_agg4[N_MAX * (DH / 4)];   // message aggregation
__device__ float  g_deg[N_MAX];   // starts 0; K1 accumulates; k_final resets to 0

// ---------------------------------------------------------------------------
// K1 (fused): blocks [0, TB): node transform + u/v projection (smem-staged);
// blocks [TB, TB+DB): one-shot source-node out-degree atomics.
// Transform x reads vectorized (LDS.128); tf fused scalar-free order-preserving.
// ---------------------------------------------------------------------------
#define XSTR 68   // padded node row stride (floats): float4-aligned, conflict-free

__global__ void __launch_bounds__(256) k_transform_deg_uv(
        const float* __restrict__ x,
        const float* __restrict__ W1,
        const float* __restrict__ W2,
        const float* __restrict__ m1w,
        const int* __restrict__ ei,
        int N, int E, int TB) {
    __shared__ float W1s[16];
    __shared__ __align__(16) float W2s[256];
    __shared__ __align__(16) float xs[64 * XSTR];   // 64 nodes staged / xf overwrite
    // uv weights at row (q*4 + part): part-stride 68 = 4 (mod 32) -> conflict-free.
    __shared__ __align__(16) float wt[32 * XSTR];

    int tid = threadIdx.x;

    if (blockIdx.x >= TB) {
        // ---- degree part: one-shot blocks (overlap transform blocks) ----
        int e = (blockIdx.x - TB) * 256 + tid;
        if (e < E) atomicAdd(&g_deg[ei[e]], 1.0f);
        return;
    }

    if (tid < 16) W1s[tid] = W1[tid];
    for (int i = tid; i < 256; i += 256) W2s[i] = W2[i];
    for (int i = tid; i < 32 * 64; i += 256) {
        int oi = i >> 6;
        int k  = i & 63;
        int part = oi >> 3;
        int q    = oi & 7;
        float wv = (oi < 16) ? m1w[oi * 128 + k]
                             : m1w[(oi - 16) * 128 + 64 + k];
        wt[(q * 4 + part) * XSTR + k] = wv;
    }

    int nbase = blockIdx.x * 64;
    int navail = N - nbase;
    int nloc = navail >= 64 ? 64 : navail;
    int total = nloc * 64;
#pragma unroll 4
    for (int i = tid; i < total; i += 256) {
        int nl = i >> 6;
        int k  = i & 63;
        xs[nl * XSTR + k] = x[(size_t)nbase * 64 + i];
    }
    __syncthreads();

    int nl = tid >> 2;           // local node 0..63
    int d  = tid & 3;
    int n  = nbase + nl;

    float4 o4[4];
    if (n < N) {
        const float4* xr4 = (const float4*)(xs + nl * XSTR);
        const float4* W2s4 = (const float4*)W2s;
        float w0 = W1s[d], w1 = W1s[4 + d], w2w = W1s[8 + d], w3 = W1s[12 + d];
#pragma unroll
        for (int g4 = 0; g4 < 4; ++g4) o4[g4] = make_float4(0.f, 0.f, 0.f, 0.f);
#pragma unroll
        for (int f4 = 0; f4 < 4; ++f4) {
            // tf for 4 consecutive f; same per-component order: dd ascending
            float4 xa = xr4[f4];          // dd=0
            float4 xb = xr4[4 + f4];      // dd=1
            float4 xc = xr4[8 + f4];      // dd=2
            float4 xd = xr4[12 + f4];     // dd=3
            float4 tf4;
            tf4.x = ((w0 * xa.x + w1 * xb.x) + w2w * xc.x) + w3 * xd.x;
            tf4.y = ((w0 * xa.y + w1 * xb.y) + w2w * xc.y) + w3 * xd.y;
            tf4.z = ((w0 * xa.z + w1 * xb.z) + w2w * xc.z) + w3 * xd.z;
            tf4.w = ((w0 * xa.w + w1 * xb.w) + w2w * xc.w) + w3 * xd.w;
#pragma unroll
            for (int r = 0; r < 4; ++r) {
                int f = f4 * 4 + r;
                float tf = (r == 0) ? tf4.x : (r == 1) ? tf4.y : (r == 2) ? tf4.z : tf4.w;
#pragma unroll
                for (int g4 = 0; g4 < 4; ++g4) {
                    float4 wv = W2s4[f * 4 + g4];
                    o4[g4].x += tf * wv.x;
                    o4[g4].y += tf * wv.y;
                    o4[g4].z += tf * wv.z;
                    o4[g4].w += tf * wv.w;
                }
            }
        }
    }
    __syncthreads();   // all xs reads done before overwrite

    if (n < N) {
        float4* xf4  = g_xf4  + (size_t)n * 16 + d * 4;
        float4* agg4 = g_agg4 + (size_t)n * 16 + d * 4;
        float4* xrow = (float4*)(xs + nl * XSTR) + d * 4;
#pragma unroll
        for (int g4 = 0; g4 < 4; ++g4) {
            xf4[g4]  = o4[g4];
            xrow[g4] = o4[g4];
            agg4[g4] = make_float4(0.f, 0.f, 0.f, 0.f);
        }
    }
    __syncthreads();

    // ---- uv: 128 threads, each computes 8 outputs for TWO nodes ----
    if (tid < 128) {
        int part = tid & 3;
        int nb   = tid >> 2;
        int n0 = nbase + nb;
        int n1 = nbase + nb + 32;
        bool v0 = (n0 < N);
        bool v1 = (n1 < N);

        const float4* xa4 = (const float4*)(xs + nb * XSTR);
        const float4* xb4 = (const float4*)(xs + (nb + 32) * XSTR);

        float acc0[8], acc1[8];
#pragma unroll
        for (int q = 0; q < 8; ++q) { acc0[q] = 0.f; acc1[q] = 0.f; }

#pragma unroll
        for (int k4 = 0; k4 < 16; ++k4) {
            float4 xa = v0 ? xa4[k4] : make_float4(0.f, 0.f, 0.f, 0.f);
            float4 xb = v1 ? xb4[k4] : make_float4(0.f, 0.f, 0.f, 0.f);
#pragma unroll
            for (int q = 0; q < 8; ++q) {
                const float4 wv = *(const float4*)(wt + (q * 4 + part) * XSTR + k4 * 4);
                acc0[q] += wv.x * xa.x + wv.y * xa.y + wv.z * xa.z + wv.w * xa.w;
                acc1[q] += wv.x * xb.x + wv.y * xb.y + wv.z * xb.z + wv.w * xb.w;
            }
        }
        if (v0) {
            float4* uvp = (float4*)((float*)(g_uv4 + (size_t)n0 * 8) + part * 8);
            uvp[0] = make_float4(acc0[0], acc0[1], acc0[2], acc0[3]);
            uvp[1] = make_float4(acc0[4], acc0[5], acc0[6], acc0[7]);
        }
        if (v1) {
            float4* uvp = (float4*)((float*)(g_uv4 + (size_t)n1 * 8) + part * 8);
            uvp[0] = make_float4(acc1[0], acc1[1], acc1[2], acc1[3]);
            uvp[1] = make_float4(acc1[4], acc1[5], acc1[6], acc1[7]);
        }
    }
}

// ---------------------------------------------------------------------------
// MGS QR of A = I + strictly-lower(params). Q[col][row].
// ---------------------------------------------------------------------------
__device__ __forceinline__ void qr4(const float p[6], float Q[4][4]) {
    const float a[4][4] = {
        {1.f,  p[0], p[1], p[3]},
        {0.f,  1.f,  p[2], p[4]},
        {0.f,  0.f,  1.f,  p[5]},
        {0.f,  0.f,  0.f,  1.f }};
#pragma unroll
    for (int c = 0; c < 4; ++c) {
        float v0 = a[c][0], v1 = a[c][1], v2 = a[c][2], v3 = a[c][3];
#pragma unroll
        for (int j = 0; j < c; ++j) {
            float r = v0 * Q[j][0] + v1 * Q[j][1] + v2 * Q[j][2] + v3 * Q[j][3];
            v0 -= r * Q[j][0];
            v1 -= r * Q[j][1];
            v2 -= r * Q[j][2];
            v3 -= r * Q[j][3];
        }
        float inv = rsqrtf(v0 * v0 + v1 * v1 + v2 * v2 + v3 * v3);
        Q[c][0] = v0 * inv; Q[c][1] = v1 * inv; Q[c][2] = v2 * inv; Q[c][3] = v3 * inv;
    }
}

__device__ __forceinline__ void red4(float4* addr, float4 v) {
    asm volatile("red.global.add.v4.f32 [%0], {%1, %2, %3, %4};"
                 :: "l"(addr), "f"(v.x), "f"(v.y), "f"(v.z), "f"(v.w)
                 : "memory");
}

// ---------------------------------------------------------------------------
// K2: phase-cooperative edge kernel (round-13 winner, unchanged).
// ---------------------------------------------------------------------------
#define ROWS 36  // floats per edge row: 32 + pad; 144B = 16B-aligned, bank-clean

__global__ void __launch_bounds__(128, 8) k_edge(
        const int* __restrict__ ei,
        const float* __restrict__ b1,
        const float* __restrict__ w2,
        const float* __restrict__ b2,
        int E) {
    __shared__ __align__(16) float s_h[4][32 * ROWS];
    __shared__ __align__(16) float b1s[16];
    __shared__ float w2p[128];   // w2p[t*8+c], padded
    __shared__ float b2s[8];

    int tid = threadIdx.x;
    if (tid < 16) b1s[tid] = b1[tid];
    if (tid < 128) w2p[tid] = ((tid & 7) < 6) ? w2[(tid & 7) * 16 + (tid >> 3)] : 0.f;
    if (tid < 6)  b2s[tid] = b2[tid];
    __syncthreads();

    int lane = tid & 31;
    int w    = tid >> 5;
    float* Hs = s_h[w];

    int ebase = (blockIdx.x * 4 + w) * 32;
    int eg = ebase + lane;

    int rj = 0, ci = 0;
    if (eg < E) {
        rj = ei[eg];
        ci = ei[E + eg];
    }
    float s = rsqrtf((1.0f + g_deg[ci]) * (1.0f + g_deg[rj]));

    // ---- Phase A: 8 lanes per edge, float4 quarters, fused relu-combine ----
    {
        const float4* uv4base = (const float4*)g_uv4;
        int sub = lane & 7;
        int esl = lane >> 3;                       // 0..3: edge slot per iter
        float4 b1v = ((const float4*)b1s)[sub & 3];
#pragma unroll
        for (int g = 0; g < 8; ++g) {
            int eid = g * 4 + esl;
            int rje = __shfl_sync(0xffffffffu, rj, eid);
            int cie = __shfl_sync(0xffffffffu, ci, eid);
            float4 ui4 = __ldg(uv4base + (size_t)cie * 8 + sub);
            float4 uj4 = __ldg(uv4base + (size_t)rje * 8 + sub);
            float4 oj;
            oj.x = __shfl_xor_sync(0xffffffffu, uj4.x, 4);
            oj.y = __shfl_xor_sync(0xffffffffu, uj4.y, 4);
            oj.z = __shfl_xor_sync(0xffffffffu, uj4.z, 4);
            oj.w = __shfl_xor_sync(0xffffffffu, uj4.w, 4);
            float4 h;
            h.x = fmaxf(ui4.x + oj.x + b1v.x, 0.f);
            h.y = fmaxf(ui4.y + oj.y + b1v.y, 0.f);
            h.z = fmaxf(ui4.z + oj.z + b1v.z, 0.f);
            h.w = fmaxf(ui4.w + oj.w + b1v.w, 0.f);
            ((float4*)(Hs + eid * ROWS))[sub] = h;
        }
    }
    __syncwarp();

    // ---- Phase B: thread-per-edge mlp2 + QR + M ----
    {
        const float4* hrow = (const float4*)(Hs + lane * ROWS);
        float h_all[32];
#pragma unroll
        for (int q = 0; q < 8; ++q) {
            float4 v = hrow[q];
            h_all[q * 4 + 0] = v.x;
            h_all[q * 4 + 1] = v.y;
            h_all[q * 4 + 2] = v.z;
            h_all[q * 4 + 3] = v.w;
        }

        float pve[6], pue[6];
#pragma unroll
        for (int c = 0; c < 6; ++c) { pve[c] = b2s[c]; pue[c] = b2s[c]; }
#pragma unroll
        for (int t = 0; t < 16; ++t) {
            float4 wA = *(const float4*)(w2p + t * 8);
            float4 wB = *(const float4*)(w2p + t * 8 + 4);
            float hv = h_all[t];
            float hu = h_all[16 + t];
            pve[0] += wA.x * hv;  pue[0] += wA.x * hu;
            pve[1] += wA.y * hv;  pue[1] += wA.y * hu;
            pve[2] += wA.z * hv;  pue[2] += wA.z * hu;
            pve[3] += wA.w * hv;  pue[3] += wA.w * hu;
            pve[4] += wB.x * hv;  pue[4] += wB.x * hu;
            pve[5] += wB.y * hv;  pue[5] += wB.y * hu;
        }

        float Qv[4][4], Qu[4][4];
        qr4(pve, Qv);
        qr4(pue, Qu);

        float4* Mrow = (float4*)(Hs + lane * ROWS);
#pragma unroll
        for (int a = 0; a < 4; ++a) {
            float4 m;
            m.x = s * (Qv[a][0] * Qu[0][0] + Qv[a][1] * Qu[0][1] + Qv[a][2] * Qu[0][2] + Qv[a][3] * Qu[0][3]);
            m.y = s * (Qv[a][0] * Qu[1][0] + Qv[a][1] * Qu[1][1] + Qv[a][2] * Qu[1][2] + Qv[a][3] * Qu[1][3]);
            m.z = s * (Qv[a][0] * Qu[2][0] + Qv[a][1] * Qu[2][1] + Qv[a][2] * Qu[2][2] + Qv[a][3] * Qu[2][3]);
            m.w = s * (Qv[a][0] * Qu[3][0] + Qv[a][1] * Qu[3][1] + Qv[a][2] * Qu[3][2] + Qv[a][3] * Qu[3][3]);
            Mrow[a] = m;
        }
    }
    __syncwarp();

    // ---- Phase C: 16 lanes per edge, 2 edges per step ----
    int half = lane >> 4;
    int sub  = lane & 15;
    int a    = sub >> 2;
    int h4   = sub & 3;

#pragma unroll 4
    for (int it = 0; it < 16; ++it) {
        int e = it * 2 + half;
        int rje = __shfl_sync(0xffffffffu, rj, e);
        int cie = __shfl_sync(0xffffffffu, ci, e);

        const float4* xj4 = g_xf4 + (size_t)rje * 16;
        float4 x0 = __ldg(xj4 + 0 * 4 + h4);
        float4 x1 = __ldg(xj4 + 1 * 4 + h4);
        float4 x2 = __ldg(xj4 + 2 * 4 + h4);
        float4 x3 = __ldg(xj4 + 3 * 4 + h4);

        float4 mr = *(const float4*)(Hs + e * ROWS + a * 4);

        float4 m;
        m.x = mr.x * x0.x + mr.y * x1.x + mr.z * x2.x + mr.w * x3.x;
        m.y = mr.x * x0.y + mr.y * x1.y + mr.z * x2.y + mr.w * x3.y;
        m.z = mr.x * x0.z + mr.y * x1.z + mr.z * x2.z + mr.w * x3.z;
        m.w = mr.x * x0.w + mr.y * x1.w + mr.z * x2.w + mr.w * x3.w;

        if (ebase + e < E)
            red4(g_agg4 + (size_t)cie * 16 + a * 4 + h4, m);
    }
}

// ---------------------------------------------------------------------------
// K3: out = (1 + tanh(eps_d)) * x - elu(agg + xf/(1+deg)); resets deg -> 0.
// ---------------------------------------------------------------------------
__global__ void k_final(const float* __restrict__ x,
                        const float* __restrict__ eps,
                        float* __restrict__ out, int N) {
    int i = blockIdx.x * blockDim.x + threadIdx.x;   // float4 index
    if (i >= N * 16) return;
    int n = i >> 4;
    int d = (i >> 2) & 3;
    float coeff = 1.0f + tanhf(__ldg(eps + d));
    float degv = g_deg[n];
    float ds2 = 1.0f / (1.0f + degv);

    float4 ag = g_agg4[i];
    float4 xf = g_xf4[i];
    float4 xv = ((const float4*)x)[i];

    float a0 = ag.x + ds2 * xf.x;
    float a1 = ag.y + ds2 * xf.y;
    float a2 = ag.z + ds2 * xf.z;
    float a3 = ag.w + ds2 * xf.w;

    float4 o;
    o.x = coeff * xv.x - (a0 > 0.f ? a0 : expm1f(a0));
    o.y = coeff * xv.y - (a1 > 0.f ? a1 : expm1f(a1));
    o.z = coeff * xv.z - (a2 > 0.f ? a2 : expm1f(a2));
    o.w = coeff * xv.w - (a3 > 0.f ? a3 : expm1f(a3));
    ((float4*)out)[i] = o;

    if ((i & 15) == 0) g_deg[n] = 0.f;   // reset for next graph replay
}

// ---------------------------------------------------------------------------
extern "C" void kernel_launch(void* const* d_in, const int* in_sizes, int n_in,
                              void* d_out, int out_size) {
    const float* x   = (const float*)d_in[0];
    const int*   ei  = (const int*)d_in[1];   // int32 (JAX x64 disabled)
    const float* W1  = (const float*)d_in[2];
    const float* W2  = (const float*)d_in[3];
    const float* eps = (const float*)d_in[4];
    const float* m1w = (const float*)d_in[5];
    const float* m1b = (const float*)d_in[6];
    const float* m2w = (const float*)d_in[7];
    const float* m2b = (const float*)d_in[8];

    int N = in_sizes[0] / DH;
    int E = in_sizes[1] / 2;

    int TB = (N + 63) / 64;          // transform blocks (64 nodes each)
    int DB = (E + 255) / 256;        // one-shot degree blocks

    k_transform_deg_uv<<<TB + DB, 256>>>(x, W1, W2, m1w, ei, N, E, TB);
    k_edge<<<(E + 127) / 128, 128>>>(ei, m1b, m2w, m2b, E);
    k_final<<<(N * 16 + 255) / 256, 256>>>(x, eps, (float*)d_out, N);
}

// round 16
// speedup vs baseline: 1.1226x; 1.0068x over previous
#include <cuda_runtime.h>
#include <math.h>

#define D 4
#define H 16
#define DH 64

#define N_MAX 65536

// Scratch (device globals). 256B alignment -> whole 128B lines per node.
__device__ __align__(256) float4 g_xf4[N_MAX * (DH / 4)];    // transformed features
__device__ __align__(256) float4 g_uv4[N_MAX * 8];           // per-node u(16), v(16)
__device__ __align__(256) float4 g_agg4[N_MAX * (DH / 4)];   // message aggregation
__device__ float  g_deg[N_MAX];   // starts 0; K1 accumulates; k_final resets to 0

// ---------------------------------------------------------------------------
// K1 (fused): blocks [0, TB): node transform + u/v projection (smem-staged);
// blocks [TB, TB+DB): one-shot source-node out-degree atomics.
// (round-15 winner, unchanged)
// ---------------------------------------------------------------------------
#define XSTR 68   // padded node row stride (floats): float4-aligned, conflict-free

__global__ void __launch_bounds__(256) k_transform_deg_uv(
        const float* __restrict__ x,
        const float* __restrict__ W1,
        const float* __restrict__ W2,
        const float* __restrict__ m1w,
        const int* __restrict__ ei,
        int N, int E, int TB) {
    __shared__ float W1s[16];
    __shared__ __align__(16) float W2s[256];
    __shared__ __align__(16) float xs[64 * XSTR];   // 64 nodes staged / xf overwrite
    __shared__ __align__(16) float wt[32 * XSTR];

    int tid = threadIdx.x;

    if (blockIdx.x >= TB) {
        int e = (blockIdx.x - TB) * 256 + tid;
        if (e < E) atomicAdd(&g_deg[ei[e]], 1.0f);
        return;
    }

    if (tid < 16) W1s[tid] = W1[tid];
    for (int i = tid; i < 256; i += 256) W2s[i] = W2[i];
    for (int i = tid; i < 32 * 64; i += 256) {
        int oi = i >> 6;
        int k  = i & 63;
        int part = oi >> 3;
        int q    = oi & 7;
        float wv = (oi < 16) ? m1w[oi * 128 + k]
                             : m1w[(oi - 16) * 128 + 64 + k];
        wt[(q * 4 + part) * XSTR + k] = wv;
    }

    int nbase = blockIdx.x * 64;
    int navail = N - nbase;
    int nloc = navail >= 64 ? 64 : navail;
    int total = nloc * 64;
#pragma unroll 4
    for (int i = tid; i < total; i += 256) {
        int nl = i >> 6;
        int k  = i & 63;
        xs[nl * XSTR + k] = x[(size_t)nbase * 64 + i];
    }
    __syncthreads();

    int nl = tid >> 2;           // local node 0..63
    int d  = tid & 3;
    int n  = nbase + nl;

    float4 o4[4];
    if (n < N) {
        const float4* xr4 = (const float4*)(xs + nl * XSTR);
        const float4* W2s4 = (const float4*)W2s;
        float w0 = W1s[d], w1 = W1s[4 + d], w2w = W1s[8 + d], w3 = W1s[12 + d];
#pragma unroll
        for (int g4 = 0; g4 < 4; ++g4) o4[g4] = make_float4(0.f, 0.f, 0.f, 0.f);
#pragma unroll
        for (int f4 = 0; f4 < 4; ++f4) {
            float4 xa = xr4[f4];          // dd=0
            float4 xb = xr4[4 + f4];      // dd=1
            float4 xc = xr4[8 + f4];      // dd=2
            float4 xd = xr4[12 + f4];     // dd=3
            float4 tf4;
            tf4.x = ((w0 * xa.x + w1 * xb.x) + w2w * xc.x) + w3 * xd.x;
            tf4.y = ((w0 * xa.y + w1 * xb.y) + w2w * xc.y) + w3 * xd.y;
            tf4.z = ((w0 * xa.z + w1 * xb.z) + w2w * xc.z) + w3 * xd.z;
            tf4.w = ((w0 * xa.w + w1 * xb.w) + w2w * xc.w) + w3 * xd.w;
#pragma unroll
            for (int r = 0; r < 4; ++r) {
                int f = f4 * 4 + r;
                float tf = (r == 0) ? tf4.x : (r == 1) ? tf4.y : (r == 2) ? tf4.z : tf4.w;
#pragma unroll
                for (int g4 = 0; g4 < 4; ++g4) {
                    float4 wv = W2s4[f * 4 + g4];
                    o4[g4].x += tf * wv.x;
                    o4[g4].y += tf * wv.y;
                    o4[g4].z += tf * wv.z;
                    o4[g4].w += tf * wv.w;
                }
            }
        }
    }
    __syncthreads();   // all xs reads done before overwrite

    if (n < N) {
        float4* xf4  = g_xf4  + (size_t)n * 16 + d * 4;
        float4* agg4 = g_agg4 + (size_t)n * 16 + d * 4;
        float4* xrow = (float4*)(xs + nl * XSTR) + d * 4;
#pragma unroll
        for (int g4 = 0; g4 < 4; ++g4) {
            xf4[g4]  = o4[g4];
            xrow[g4] = o4[g4];
            agg4[g4] = make_float4(0.f, 0.f, 0.f, 0.f);
        }
    }
    __syncthreads();

    // ---- uv: 128 threads, each computes 8 outputs for TWO nodes ----
    if (tid < 128) {
        int part = tid & 3;
        int nb   = tid >> 2;
        int n0 = nbase + nb;
        int n1 = nbase + nb + 32;
        bool v0 = (n0 < N);
        bool v1 = (n1 < N);

        const float4* xa4 = (const float4*)(xs + nb * XSTR);
        const float4* xb4 = (const float4*)(xs + (nb + 32) * XSTR);

        float acc0[8], acc1[8];
#pragma unroll
        for (int q = 0; q < 8; ++q) { acc0[q] = 0.f; acc1[q] = 0.f; }

#pragma unroll
        for (int k4 = 0; k4 < 16; ++k4) {
            float4 xa = v0 ? xa4[k4] : make_float4(0.f, 0.f, 0.f, 0.f);
            float4 xb = v1 ? xb4[k4] : make_float4(0.f, 0.f, 0.f, 0.f);
#pragma unroll
            for (int q = 0; q < 8; ++q) {
                const float4 wv = *(const float4*)(wt + (q * 4 + part) * XSTR + k4 * 4);
                acc0[q] += wv.x * xa.x + wv.y * xa.y + wv.z * xa.z + wv.w * xa.w;
                acc1[q] += wv.x * xb.x + wv.y * xb.y + wv.z * xb.z + wv.w * xb.w;
            }
        }
        if (v0) {
            float4* uvp = (float4*)((float*)(g_uv4 + (size_t)n0 * 8) + part * 8);
            uvp[0] = make_float4(acc0[0], acc0[1], acc0[2], acc0[3]);
            uvp[1] = make_float4(acc0[4], acc0[5], acc0[6], acc0[7]);
        }
        if (v1) {
            float4* uvp = (float4*)((float*)(g_uv4 + (size_t)n1 * 8) + part * 8);
            uvp[0] = make_float4(acc1[0], acc1[1], acc1[2], acc1[3]);
            uvp[1] = make_float4(acc1[4], acc1[5], acc1[6], acc1[7]);
        }
    }
}

// ---------------------------------------------------------------------------
// MGS QR of A = I + strictly-lower(params). Q[col][row].
// ---------------------------------------------------------------------------
__device__ __forceinline__ void qr4(const float p[6], float Q[4][4]) {
    const float a[4][4] = {
        {1.f,  p[0], p[1], p[3]},
        {0.f,  1.f,  p[2], p[4]},
        {0.f,  0.f,  1.f,  p[5]},
        {0.f,  0.f,  0.f,  1.f }};
#pragma unroll
    for (int c = 0; c < 4; ++c) {
        float v0 = a[c][0], v1 = a[c][1], v2 = a[c][2], v3 = a[c][3];
#pragma unroll
        for (int j = 0; j < c; ++j) {
            float r = v0 * Q[j][0] + v1 * Q[j][1] + v2 * Q[j][2] + v3 * Q[j][3];
            v0 -= r * Q[j][0];
            v1 -= r * Q[j][1];
            v2 -= r * Q[j][2];
            v3 -= r * Q[j][3];
        }
        float inv = rsqrtf(v0 * v0 + v1 * v1 + v2 * v2 + v3 * v3);
        Q[c][0] = v0 * inv; Q[c][1] = v1 * inv; Q[c][2] = v2 * inv; Q[c][3] = v3 * inv;
    }
}

__device__ __forceinline__ void red4(float4* addr, float4 v) {
    asm volatile("red.global.add.v4.f32 [%0], {%1, %2, %3, %4};"
                 :: "l"(addr), "f"(v.x), "f"(v.y), "f"(v.z), "f"(v.w)
                 : "memory");
}

// ---------------------------------------------------------------------------
// K2: phase-cooperative edge kernel. Phase C reworked: single LDG per
// iteration (lane owns its own float4 of xj), rows redistributed via
// shfl_xor(4/8/12); M stored xor-permuted at Phase-B write (compile-time).
// ---------------------------------------------------------------------------
#define ROWS 36  // floats per edge row: 32 + pad; 144B = 16B-aligned, bank-clean

__global__ void __launch_bounds__(128, 8) k_edge(
        const int* __restrict__ ei,
        const float* __restrict__ b1,
        const float* __restrict__ w2,
        const float* __restrict__ b2,
        int E) {
    __shared__ __align__(16) float s_h[4][32 * ROWS];
    __shared__ __align__(16) float b1s[16];
    __shared__ float w2p[128];   // w2p[t*8+c], padded
    __shared__ float b2s[8];

    int tid = threadIdx.x;
    if (tid < 16) b1s[tid] = b1[tid];
    if (tid < 128) w2p[tid] = ((tid & 7) < 6) ? w2[(tid & 7) * 16 + (tid >> 3)] : 0.f;
    if (tid < 6)  b2s[tid] = b2[tid];
    __syncthreads();

    int lane = tid & 31;
    int w    = tid >> 5;
    float* Hs = s_h[w];

    int ebase = (blockIdx.x * 4 + w) * 32;
    int eg = ebase + lane;

    int rj = 0, ci = 0;
    if (eg < E) {
        rj = ei[eg];
        ci = ei[E + eg];
    }
    float s = rsqrtf((1.0f + g_deg[ci]) * (1.0f + g_deg[rj]));

    // ---- Phase A: 8 lanes per edge, float4 quarters, fused relu-combine ----
    {
        const float4* uv4base = (const float4*)g_uv4;
        int sub = lane & 7;
        int esl = lane >> 3;                       // 0..3: edge slot per iter
        float4 b1v = ((const float4*)b1s)[sub & 3];
#pragma unroll
        for (int g = 0; g < 8; ++g) {
            int eid = g * 4 + esl;
            int rje = __shfl_sync(0xffffffffu, rj, eid);
            int cie = __shfl_sync(0xffffffffu, ci, eid);
            float4 ui4 = __ldg(uv4base + (size_t)cie * 8 + sub);
            float4 uj4 = __ldg(uv4base + (size_t)rje * 8 + sub);
            float4 oj;
            oj.x = __shfl_xor_sync(0xffffffffu, uj4.x, 4);
            oj.y = __shfl_xor_sync(0xffffffffu, uj4.y, 4);
            oj.z = __shfl_xor_sync(0xffffffffu, uj4.z, 4);
            oj.w = __shfl_xor_sync(0xffffffffu, uj4.w, 4);
            float4 h;
            h.x = fmaxf(ui4.x + oj.x + b1v.x, 0.f);
            h.y = fmaxf(ui4.y + oj.y + b1v.y, 0.f);
            h.z = fmaxf(ui4.z + oj.z + b1v.z, 0.f);
            h.w = fmaxf(ui4.w + oj.w + b1v.w, 0.f);
            ((float4*)(Hs + eid * ROWS))[sub] = h;
        }
    }
    __syncwarp();

    // ---- Phase B: thread-per-edge mlp2 + QR + M (xor-permuted store) ----
    {
        const float4* hrow = (const float4*)(Hs + lane * ROWS);
        float h_all[32];
#pragma unroll
        for (int q = 0; q < 8; ++q) {
            float4 v = hrow[q];
            h_all[q * 4 + 0] = v.x;
            h_all[q * 4 + 1] = v.y;
            h_all[q * 4 + 2] = v.z;
            h_all[q * 4 + 3] = v.w;
        }

        float pve[6], pue[6];
#pragma unroll
        for (int c = 0; c < 6; ++c) { pve[c] = b2s[c]; pue[c] = b2s[c]; }
#pragma unroll
        for (int t = 0; t < 16; ++t) {
            float4 wA = *(const float4*)(w2p + t * 8);
            float4 wB = *(const float4*)(w2p + t * 8 + 4);
            float hv = h_all[t];
            float hu = h_all[16 + t];
            pve[0] += wA.x * hv;  pue[0] += wA.x * hu;
            pve[1] += wA.y * hv;  pue[1] += wA.y * hu;
            pve[2] += wA.z * hv;  pue[2] += wA.z * hu;
            pve[3] += wA.w * hv;  pue[3] += wA.w * hu;
            pve[4] += wB.x * hv;  pue[4] += wB.x * hu;
            pve[5] += wB.y * hv;  pue[5] += wB.y * hu;
        }

        float Qv[4][4], Qu[4][4];
        qr4(pve, Qv);
        qr4(pue, Qu);

        // mm[a][b] = s * sum_k Qv[a][k]*Qu[b][k]
        float mm[4][4];
#pragma unroll
        for (int a = 0; a < 4; ++a)
#pragma unroll
            for (int b = 0; b < 4; ++b)
                mm[a][b] = s * (Qv[a][0] * Qu[b][0] + Qv[a][1] * Qu[b][1] +
                                Qv[a][2] * Qu[b][2] + Qv[a][3] * Qu[b][3]);

        // Store xor-permuted: Mrow[a] = (mm[a][a^0], mm[a][a^1], mm[a][a^2], mm[a][a^3])
        float4* Mrow = (float4*)(Hs + lane * ROWS);
#pragma unroll
        for (int a = 0; a < 4; ++a)
            Mrow[a] = make_float4(mm[a][a], mm[a][a ^ 1], mm[a][a ^ 2], mm[a][a ^ 3]);
    }
    __syncwarp();

    // ---- Phase C: 16 lanes per edge, 2 edges per step, single LDG +
    //      xor-butterfly row redistribution ----
    int half = lane >> 4;
    int sub  = lane & 15;       // = a*4 + h4
    int a    = sub >> 2;        // output row (also the row of the owned float4)

#pragma unroll 4
    for (int it = 0; it < 16; ++it) {
        int e = it * 2 + half;
        int rje = __shfl_sync(0xffffffffu, rj, e);
        int cie = __shfl_sync(0xffffffffu, ci, e);

        // Lane owns x[a][h4] (the sub-th float4 of xj's row).
        float4 xv = __ldg(g_xf4 + (size_t)rje * 16 + sub);

        // Rows a^1, a^2, a^3 at same h4 via xor over lane bits 2-3.
        float4 v1, v2, v3;
        v1.x = __shfl_xor_sync(0xffffffffu, xv.x, 4);
        v1.y = __shfl_xor_sync(0xffffffffu, xv.y, 4);
        v1.z = __shfl_xor_sync(0xffffffffu, xv.z, 4);
        v1.w = __shfl_xor_sync(0xffffffffu, xv.w, 4);
        v2.x = __shfl_xor_sync(0xffffffffu, xv.x, 8);
        v2.y = __shfl_xor_sync(0xffffffffu, xv.y, 8);
        v2.z = __shfl_xor_sync(0xffffffffu, xv.z, 8);
        v2.w = __shfl_xor_sync(0xffffffffu, xv.w, 8);
        v3.x = __shfl_xor_sync(0xffffffffu, xv.x, 12);
        v3.y = __shfl_xor_sync(0xffffffffu, xv.y, 12);
        v3.z = __shfl_xor_sync(0xffffffffu, xv.z, 12);
        v3.w = __shfl_xor_sync(0xffffffffu, xv.w, 12);

        // Permuted M row: (M[a][a], M[a][a^1], M[a][a^2], M[a][a^3])
        float4 mr = *(const float4*)(Hs + e * ROWS + a * 4);

        float4 m;
        m.x = mr.x * xv.x + mr.y * v1.x + mr.z * v2.x + mr.w * v3.x;
        m.y = mr.x * xv.y + mr.y * v1.y + mr.z * v2.y + mr.w * v3.y;
        m.z = mr.x * xv.z + mr.y * v1.z + mr.z * v2.z + mr.w * v3.z;
        m.w = mr.x * xv.w + mr.y * v1.w + mr.z * v2.w + mr.w * v3.w;

        if (ebase + e < E)
            red4(g_agg4 + (size_t)cie * 16 + sub, m);
    }
}

// ---------------------------------------------------------------------------
// K3: out = (1 + tanh(eps_d)) * x - elu(agg + xf/(1+deg)); resets deg -> 0.
// ---------------------------------------------------------------------------
__global__ void k_final(const float* __restrict__ x,
                        const float* __restrict__ eps,
                        float* __restrict__ out, int N) {
    int i = blockIdx.x * blockDim.x + threadIdx.x;   // float4 index
    if (i >= N * 16) return;
    int n = i >> 4;
    int d = (i >> 2) & 3;
    float coeff = 1.0f + tanhf(__ldg(eps + d));
    float degv = g_deg[n];
    float ds2 = 1.0f / (1.0f + degv);

    float4 ag = g_agg4[i];
    float4 xf = g_xf4[i];
    float4 xv = ((const float4*)x)[i];

    float a0 = ag.x + ds2 * xf.x;
    float a1 = ag.y + ds2 * xf.y;
    float a2 = ag.z + ds2 * xf.z;
    float a3 = ag.w + ds2 * xf.w;

    float4 o;
    o.x = coeff * xv.x - (a0 > 0.f ? a0 : expm1f(a0));
    o.y = coeff * xv.y - (a1 > 0.f ? a1 : expm1f(a1));
    o.z = coeff * xv.z - (a2 > 0.f ? a2 : expm1f(a2));
    o.w = coeff * xv.w - (a3 > 0.f ? a3 : expm1f(a3));
    ((float4*)out)[i] = o;

    if ((i & 15) == 0) g_deg[n] = 0.f;   // reset for next graph replay
}

// ---------------------------------------------------------------------------
extern "C" void kernel_launch(void* const* d_in, const int* in_sizes, int n_in,
                              void* d_out, int out_size) {
    const float* x   = (const float*)d_in[0];
    const int*   ei  = (const int*)d_in[1];   // int32 (JAX x64 disabled)
    const float* W1  = (const float*)d_in[2];
    const float* W2  = (const float*)d_in[3];
    const float* eps = (const float*)d_in[4];
    const float* m1w = (const float*)d_in[5];
    const float* m1b = (const float*)d_in[6];
    const float* m2w = (const float*)d_in[7];
    const float* m2b = (const float*)d_in[8];

    int N = in_sizes[0] / DH;
    int E = in_sizes[1] / 2;

    int TB = (N + 63) / 64;          // transform blocks (64 nodes each)
    int DB = (E + 255) / 256;        // one-shot degree blocks

    k_transform_deg_uv<<<TB + DB, 256>>>(x, W1, W2, m1w, ei, N, E, TB);
    k_edge<<<(E + 127) / 128, 128>>>(ei, m1b, m2w, m2b, E);
    k_final<<<(N * 16 + 255) / 256, 256>>>(x, eps, (float*)d_out, N);
}

// round 17
// speedup vs baseline: 1.1361x; 1.0120x over previous
#include <cuda_runtime.h>
#include <math.h>

#define D 4
#define H 16
#define DH 64

#define N_MAX 65536

// Scratch (device globals). 256B alignment -> whole 128B lines per node.
__device__ __align__(256) float4 g_xf4[N_MAX * (DH / 4)];    // transformed features
__device__ __align__(256) float4 g_uv4[N_MAX * 8];           // per-node u(16), v(16)
__device__ __align__(256) float4 g_agg4[N_MAX * (DH / 4)];   // message aggregation
__device__ float  g_deg[N_MAX];   // starts 0; K1 accumulates; k_final resets to 0

// ---------------------------------------------------------------------------
// K1 (fused): blocks [0, TB): node transform + u/v projection (smem-staged);
// blocks [TB, TB+DB): one-shot source-node out-degree atomics.
// Staging loops vectorized (float4); 5 blocks/SM target.
// ---------------------------------------------------------------------------
#define XSTR 68   // padded node row stride (floats): float4-aligned, conflict-free

__global__ void __launch_bounds__(256, 5) k_transform_deg_uv(
        const float* __restrict__ x,
        const float* __restrict__ W1,
        const float* __restrict__ W2,
        const float* __restrict__ m1w,
        const int* __restrict__ ei,
        int N, int E, int TB) {
    __shared__ float W1s[16];
    __shared__ __align__(16) float W2s[256];
    __shared__ __align__(16) float xs[64 * XSTR];   // 64 nodes staged / xf overwrite
    __shared__ __align__(16) float wt[32 * XSTR];

    int tid = threadIdx.x;

    if (blockIdx.x >= TB) {
        int e = (blockIdx.x - TB) * 256 + tid;
        if (e < E) atomicAdd(&g_deg[ei[e]], 1.0f);
        return;
    }

    if (tid < 16) W1s[tid] = W1[tid];
    for (int i = tid; i < 256; i += 256) W2s[i] = W2[i];

    // wt staging, float4: 512 float4 total; row (q*4+part), conflict-free stride.
    {
        const float4* m1w4 = (const float4*)m1w;
#pragma unroll 2
        for (int i = tid; i < 512; i += 256) {
            int oi = i >> 4;                 // logical output row 0..31
            int k4 = i & 15;
            int part = oi >> 3;
            int q    = oi & 7;
            float4 wv = (oi < 16) ? __ldg(m1w4 + oi * 32 + k4)
                                  : __ldg(m1w4 + (oi - 16) * 32 + 16 + k4);
            ((float4*)(wt + (q * 4 + part) * XSTR))[k4] = wv;
        }
    }

    int nbase = blockIdx.x * 64;
    int navail = N - nbase;
    int nloc = navail >= 64 ? 64 : navail;

    // x staging, float4: nloc*16 float4.
    {
        const float4* x4 = (const float4*)x + (size_t)nbase * 16;
        int nv4 = nloc * 16;
#pragma unroll 4
        for (int i = tid; i < nv4; i += 256) {
            int nl = i >> 4;
            int k4 = i & 15;
            ((float4*)(xs + nl * XSTR))[k4] = __ldg(x4 + i);
        }
    }
    __syncthreads();

    int nl = tid >> 2;           // local node 0..63
    int d  = tid & 3;
    int n  = nbase + nl;

    float4 o4[4];
    if (n < N) {
        const float4* xr4 = (const float4*)(xs + nl * XSTR);
        const float4* W2s4 = (const float4*)W2s;
        float w0 = W1s[d], w1 = W1s[4 + d], w2w = W1s[8 + d], w3 = W1s[12 + d];
#pragma unroll
        for (int g4 = 0; g4 < 4; ++g4) o4[g4] = make_float4(0.f, 0.f, 0.f, 0.f);
#pragma unroll
        for (int f4 = 0; f4 < 4; ++f4) {
            float4 xa = xr4[f4];          // dd=0
            float4 xb = xr4[4 + f4];      // dd=1
            float4 xc = xr4[8 + f4];      // dd=2
            float4 xd = xr4[12 + f4];     // dd=3
            float4 tf4;
            tf4.x = ((w0 * xa.x + w1 * xb.x) + w2w * xc.x) + w3 * xd.x;
            tf4.y = ((w0 * xa.y + w1 * xb.y) + w2w * xc.y) + w3 * xd.y;
            tf4.z = ((w0 * xa.z + w1 * xb.z) + w2w * xc.z) + w3 * xd.z;
            tf4.w = ((w0 * xa.w + w1 * xb.w) + w2w * xc.w) + w3 * xd.w;
#pragma unroll
            for (int r = 0; r < 4; ++r) {
                int f = f4 * 4 + r;
                float tf = (r == 0) ? tf4.x : (r == 1) ? tf4.y : (r == 2) ? tf4.z : tf4.w;
#pragma unroll
                for (int g4 = 0; g4 < 4; ++g4) {
                    float4 wv = W2s4[f * 4 + g4];
                    o4[g4].x += tf * wv.x;
                    o4[g4].y += tf * wv.y;
                    o4[g4].z += tf * wv.z;
                    o4[g4].w += tf * wv.w;
                }
            }
        }
    }
    __syncthreads();   // all xs reads done before overwrite

    if (n < N) {
        float4* xf4  = g_xf4  + (size_t)n * 16 + d * 4;
        float4* agg4 = g_agg4 + (size_t)n * 16 + d * 4;
        float4* xrow = (float4*)(xs + nl * XSTR) + d * 4;
#pragma unroll
        for (int g4 = 0; g4 < 4; ++g4) {
            xf4[g4]  = o4[g4];
            xrow[g4] = o4[g4];
            agg4[g4] = make_float4(0.f, 0.f, 0.f, 0.f);
        }
    }
    __syncthreads();

    // ---- uv: 128 threads, each computes 8 outputs for TWO nodes ----
    if (tid < 128) {
        int part = tid & 3;
        int nb   = tid >> 2;
        int n0 = nbase + nb;
        int n1 = nbase + nb + 32;
        bool v0 = (n0 < N);
        bool v1 = (n1 < N);

        const float4* xa4 = (const float4*)(xs + nb * XSTR);
        const float4* xb4 = (const float4*)(xs + (nb + 32) * XSTR);

        float acc0[8], acc1[8];
#pragma unroll
        for (int q = 0; q < 8; ++q) { acc0[q] = 0.f; acc1[q] = 0.f; }

#pragma unroll
        for (int k4 = 0; k4 < 16; ++k4) {
            float4 xa = v0 ? xa4[k4] : make_float4(0.f, 0.f, 0.f, 0.f);
            float4 xb = v1 ? xb4[k4] : make_float4(0.f, 0.f, 0.f, 0.f);
#pragma unroll
            for (int q = 0; q < 8; ++q) {
                const float4 wv = *(const float4*)(wt + (q * 4 + part) * XSTR + k4 * 4);
                acc0[q] += wv.x * xa.x + wv.y * xa.y + wv.z * xa.z + wv.w * xa.w;
                acc1[q] += wv.x * xb.x + wv.y * xb.y + wv.z * xb.z + wv.w * xb.w;
            }
        }
        if (v0) {
            float4* uvp = (float4*)((float*)(g_uv4 + (size_t)n0 * 8) + part * 8);
            uvp[0] = make_float4(acc0[0], acc0[1], acc0[2], acc0[3]);
            uvp[1] = make_float4(acc0[4], acc0[5], acc0[6], acc0[7]);
        }
        if (v1) {
            float4* uvp = (float4*)((float*)(g_uv4 + (size_t)n1 * 8) + part * 8);
            uvp[0] = make_float4(acc1[0], acc1[1], acc1[2], acc1[3]);
            uvp[1] = make_float4(acc1[4], acc1[5], acc1[6], acc1[7]);
        }
    }
}

// ---------------------------------------------------------------------------
// MGS QR of A = I + strictly-lower(params). Q[col][row].
// ---------------------------------------------------------------------------
__device__ __forceinline__ void qr4(const float p[6], float Q[4][4]) {
    const float a[4][4] = {
        {1.f,  p[0], p[1], p[3]},
        {0.f,  1.f,  p[2], p[4]},
        {0.f,  0.f,  1.f,  p[5]},
        {0.f,  0.f,  0.f,  1.f }};
#pragma unroll
    for (int c = 0; c < 4; ++c) {
        float v0 = a[c][0], v1 = a[c][1], v2 = a[c][2], v3 = a[c][3];
#pragma unroll
        for (int j = 0; j < c; ++j) {
            float r = v0 * Q[j][0] + v1 * Q[j][1] + v2 * Q[j][2] + v3 * Q[j][3];
            v0 -= r * Q[j][0];
            v1 -= r * Q[j][1];
            v2 -= r * Q[j][2];
            v3 -= r * Q[j][3];
        }
        float inv = rsqrtf(v0 * v0 + v1 * v1 + v2 * v2 + v3 * v3);
        Q[c][0] = v0 * inv; Q[c][1] = v1 * inv; Q[c][2] = v2 * inv; Q[c][3] = v3 * inv;
    }
}

__device__ __forceinline__ void red4(float4* addr, float4 v) {
    asm volatile("red.global.add.v4.f32 [%0], {%1, %2, %3, %4};"
                 :: "l"(addr), "f"(v.x), "f"(v.y), "f"(v.z), "f"(v.w)
                 : "memory");
}

// ---------------------------------------------------------------------------
// K2: phase-cooperative edge kernel (round-16 version, unchanged).
// ---------------------------------------------------------------------------
#define ROWS 36  // floats per edge row: 32 + pad; 144B = 16B-aligned, bank-clean

__global__ void __launch_bounds__(128, 8) k_edge(
        const int* __restrict__ ei,
        const float* __restrict__ b1,
        const float* __restrict__ w2,
        const float* __restrict__ b2,
        int E) {
    __shared__ __align__(16) float s_h[4][32 * ROWS];
    __shared__ __align__(16) float b1s[16];
    __shared__ float w2p[128];   // w2p[t*8+c], padded
    __shared__ float b2s[8];

    int tid = threadIdx.x;
    if (tid < 16) b1s[tid] = b1[tid];
    if (tid < 128) w2p[tid] = ((tid & 7) < 6) ? w2[(tid & 7) * 16 + (tid >> 3)] : 0.f;
    if (tid < 6)  b2s[tid] = b2[tid];
    __syncthreads();

    int lane = tid & 31;
    int w    = tid >> 5;
    float* Hs = s_h[w];

    int ebase = (blockIdx.x * 4 + w) * 32;
    int eg = ebase + lane;

    int rj = 0, ci = 0;
    if (eg < E) {
        rj = ei[eg];
        ci = ei[E + eg];
    }
    float s = rsqrtf((1.0f + g_deg[ci]) * (1.0f + g_deg[rj]));

    // ---- Phase A: 8 lanes per edge, float4 quarters, fused relu-combine ----
    {
        const float4* uv4base = (const float4*)g_uv4;
        int sub = lane & 7;
        int esl = lane >> 3;                       // 0..3: edge slot per iter
        float4 b1v = ((const float4*)b1s)[sub & 3];
#pragma unroll
        for (int g = 0; g < 8; ++g) {
            int eid = g * 4 + esl;
            int rje = __shfl_sync(0xffffffffu, rj, eid);
            int cie = __shfl_sync(0xffffffffu, ci, eid);
            float4 ui4 = __ldg(uv4base + (size_t)cie * 8 + sub);
            float4 uj4 = __ldg(uv4base + (size_t)rje * 8 + sub);
            float4 oj;
            oj.x = __shfl_xor_sync(0xffffffffu, uj4.x, 4);
            oj.y = __shfl_xor_sync(0xffffffffu, uj4.y, 4);
            oj.z = __shfl_xor_sync(0xffffffffu, uj4.z, 4);
            oj.w = __shfl_xor_sync(0xffffffffu, uj4.w, 4);
            float4 h;
            h.x = fmaxf(ui4.x + oj.x + b1v.x, 0.f);
            h.y = fmaxf(ui4.y + oj.y + b1v.y, 0.f);
            h.z = fmaxf(ui4.z + oj.z + b1v.z, 0.f);
            h.w = fmaxf(ui4.w + oj.w + b1v.w, 0.f);
            ((float4*)(Hs + eid * ROWS))[sub] = h;
        }
    }
    __syncwarp();

    // ---- Phase B: thread-per-edge mlp2 + QR + M (xor-permuted store) ----
    {
        const float4* hrow = (const float4*)(Hs + lane * ROWS);
        float h_all[32];
#pragma unroll
        for (int q = 0; q < 8; ++q) {
            float4 v = hrow[q];
            h_all[q * 4 + 0] = v.x;
            h_all[q * 4 + 1] = v.y;
            h_all[q * 4 + 2] = v.z;
            h_all[q * 4 + 3] = v.w;
        }

        float pve[6], pue[6];
#pragma unroll
        for (int c = 0; c < 6; ++c) { pve[c] = b2s[c]; pue[c] = b2s[c]; }
#pragma unroll
        for (int t = 0; t < 16; ++t) {
            float4 wA = *(const float4*)(w2p + t * 8);
            float4 wB = *(const float4*)(w2p + t * 8 + 4);
            float hv = h_all[t];
            float hu = h_all[16 + t];
            pve[0] += wA.x * hv;  pue[0] += wA.x * hu;
            pve[1] += wA.y * hv;  pue[1] += wA.y * hu;
            pve[2] += wA.z * hv;  pue[2] += wA.z * hu;
            pve[3] += wA.w * hv;  pue[3] += wA.w * hu;
            pve[4] += wB.x * hv;  pue[4] += wB.x * hu;
            pve[5] += wB.y * hv;  pue[5] += wB.y * hu;
        }

        float Qv[4][4], Qu[4][4];
        qr4(pve, Qv);
        qr4(pue, Qu);

        float mm[4][4];
#pragma unroll
        for (int a = 0; a < 4; ++a)
#pragma unroll
            for (int b = 0; b < 4; ++b)
                mm[a][b] = s * (Qv[a][0] * Qu[b][0] + Qv[a][1] * Qu[b][1] +
                                Qv[a][2] * Qu[b][2] + Qv[a][3] * Qu[b][3]);

        float4* Mrow = (float4*)(Hs + lane * ROWS);
#pragma unroll
        for (int a = 0; a < 4; ++a)
            Mrow[a] = make_float4(mm[a][a], mm[a][a ^ 1], mm[a][a ^ 2], mm[a][a ^ 3]);
    }
    __syncwarp();

    // ---- Phase C: 16 lanes per edge, 2 edges per step, single LDG +
    //      xor-butterfly row redistribution ----
    int half = lane >> 4;
    int sub  = lane & 15;       // = a*4 + h4
    int a    = sub >> 2;

#pragma unroll 4
    for (int it = 0; it < 16; ++it) {
        int e = it * 2 + half;
        int rje = __shfl_sync(0xffffffffu, rj, e);
        int cie = __shfl_sync(0xffffffffu, ci, e);

        float4 xv = __ldg(g_xf4 + (size_t)rje * 16 + sub);

        float4 v1, v2, v3;
        v1.x = __shfl_xor_sync(0xffffffffu, xv.x, 4);
        v1.y = __shfl_xor_sync(0xffffffffu, xv.y, 4);
        v1.z = __shfl_xor_sync(0xffffffffu, xv.z, 4);
        v1.w = __shfl_xor_sync(0xffffffffu, xv.w, 4);
        v2.x = __shfl_xor_sync(0xffffffffu, xv.x, 8);
        v2.y = __shfl_xor_sync(0xffffffffu, xv.y, 8);
        v2.z = __shfl_xor_sync(0xffffffffu, xv.z, 8);
        v2.w = __shfl_xor_sync(0xffffffffu, xv.w, 8);
        v3.x = __shfl_xor_sync(0xffffffffu, xv.x, 12);
        v3.y = __shfl_xor_sync(0xffffffffu, xv.y, 12);
        v3.z = __shfl_xor_sync(0xffffffffu, xv.z, 12);
        v3.w = __shfl_xor_sync(0xffffffffu, xv.w, 12);

        float4 mr = *(const float4*)(Hs + e * ROWS + a * 4);

        float4 m;
        m.x = mr.x * xv.x + mr.y * v1.x + mr.z * v2.x + mr.w * v3.x;
        m.y = mr.x * xv.y + mr.y * v1.y + mr.z * v2.y + mr.w * v3.y;
        m.z = mr.x * xv.z + mr.y * v1.z + mr.z * v2.z + mr.w * v3.z;
        m.w = mr.x * xv.w + mr.y * v1.w + mr.z * v2.w + mr.w * v3.w;

        if (ebase + e < E)
            red4(g_agg4 + (size_t)cie * 16 + sub, m);
    }
}

// ---------------------------------------------------------------------------
// K3: out = (1 + tanh(eps_d)) * x - elu(agg + xf/(1+deg)); resets deg -> 0.
// ---------------------------------------------------------------------------
__global__ void k_final(const float* __restrict__ x,
                        const float* __restrict__ eps,
                        float* __restrict__ out, int N) {
    int i = blockIdx.x * blockDim.x + threadIdx.x;   // float4 index
    if (i >= N * 16) return;
    int n = i >> 4;
    int d = (i >> 2) & 3;
    float coeff = 1.0f + tanhf(__ldg(eps + d));
    float degv = g_deg[n];
    float ds2 = 1.0f / (1.0f + degv);

    float4 ag = g_agg4[i];
    float4 xf = g_xf4[i];
    float4 xv = ((const float4*)x)[i];

    float a0 = ag.x + ds2 * xf.x;
    float a1 = ag.y + ds2 * xf.y;
    float a2 = ag.z + ds2 * xf.z;
    float a3 = ag.w + ds2 * xf.w;

    float4 o;
    o.x = coeff * xv.x - (a0 > 0.f ? a0 : expm1f(a0));
    o.y = coeff * xv.y - (a1 > 0.f ? a1 : expm1f(a1));
    o.z = coeff * xv.z - (a2 > 0.f ? a2 : expm1f(a2));
    o.w = coeff * xv.w - (a3 > 0.f ? a3 : expm1f(a3));
    ((float4*)out)[i] = o;

    if ((i & 15) == 0) g_deg[n] = 0.f;   // reset for next graph replay
}

// ---------------------------------------------------------------------------
extern "C" void kernel_launch(void* const* d_in, const int* in_sizes, int n_in,
                              void* d_out, int out_size) {
    const float* x   = (const float*)d_in[0];
    const int*   ei  = (const int*)d_in[1];   // int32 (JAX x64 disabled)
    const float* W1  = (const float*)d_in[2];
    const float* W2  = (const float*)d_in[3];
    const float* eps = (const float*)d_in[4];
    const float* m1w = (const float*)d_in[5];
    const float* m1b = (const float*)d_in[6];
    const float* m2w = (const float*)d_in[7];
    const float* m2b = (const float*)d_in[8];

    int N = in_sizes[0] / DH;
    int E = in_sizes[1] / 2;

    int TB = (N + 63) / 64;          // transform blocks (64 nodes each)
    int DB = (E + 255) / 256;        // one-shot degree blocks

    k_transform_deg_uv<<<TB + DB, 256>>>(x, W1, W2, m1w, ei, N, E, TB);
    k_edge<<<(E + 127) / 128, 128>>>(ei, m1b, m2w, m2b, E);
    k_final<<<(N * 16 + 255) / 256, 256>>>(x, eps, (float*)d_out, N);
}